// round 11
// baseline (speedup 1.0000x reference)
#include <cuda_runtime.h>
#include <cuda_fp16.h>
#include <stdint.h>
#include <math.h>

#define SEQ   8192
#define INP   512
#define HYP   1024
#define HIDN  4096
#define CHUNK 128
#define NCHUNK (SEQ/CHUNK)   // 64

// ---------------- scratch (static __device__, no allocations) ----------------
__device__ __half g_xh  [SEQ*INP];
__device__ __half g_h1h [SEQ*HYP];
__device__ __half g_h2h [SEQ*HYP];
__device__ __half g_h3h [SEQ*HYP];
__device__ __half g_Gh  [SEQ*HIDN];
__device__ __half g_Bh  [SEQ*HIDN];
__device__ __half g_w15 [(HYP+HIDN)*INP];    // [w_in ; w2] rows, K=512
__device__ __half g_wI  [2*HYP*HYP];         // interleaved wg0/wg0g
__device__ __half g_wshh[HYP*HYP];
__device__ __half g_whh [HIDN*HYP];
__device__ float g_Ac[NCHUNK*HIDN];
__device__ float g_Bc[NCHUNK*HIDN];
__device__ float g_Gb[(NCHUNK+1)*HIDN];

// ---------------- PTX helpers (sm_100-portable only) --------------------------
__device__ __forceinline__ uint32_t smem_u32(const void* p) {
    uint32_t a;
    asm("{ .reg .u64 t; cvta.to.shared.u64 t, %1; cvt.u32.u64 %0, t; }" : "=r"(a) : "l"(p));
    return a;
}
__device__ __forceinline__ void cp16(uint32_t dst, const void* src) {
    asm volatile("cp.async.cg.shared.global [%0], [%1], 16;" :: "r"(dst), "l"(src));
}
__device__ __forceinline__ void cp_commit() { asm volatile("cp.async.commit_group;"); }
template <int N> __device__ __forceinline__ void cp_wait() {
    asm volatile("cp.async.wait_group %0;" :: "n"(N));
}
__device__ __forceinline__ void ldm4(uint32_t* r, uint32_t addr) {
    asm volatile("ldmatrix.sync.aligned.m8n8.x4.shared.b16 {%0,%1,%2,%3}, [%4];"
                 : "=r"(r[0]), "=r"(r[1]), "=r"(r[2]), "=r"(r[3]) : "r"(addr));
}
__device__ __forceinline__ void mma16816(float* d, const uint32_t* a, const uint32_t* b) {
    asm volatile(
        "mma.sync.aligned.m16n8k16.row.col.f32.f16.f16.f32 "
        "{%0,%1,%2,%3}, {%4,%5,%6,%7}, {%8,%9}, {%0,%1,%2,%3};"
        : "+f"(d[0]), "+f"(d[1]), "+f"(d[2]), "+f"(d[3])
        : "r"(a[0]), "r"(a[1]), "r"(a[2]), "r"(a[3]), "r"(b[0]), "r"(b[1]));
}

// ---------------- fp16 GEMM: C[M,N] = A[M,K] @ W[N,K]^T + bias ----------------
// 128x128 tile, BK=64, XOR-swizzled 128B rows, 3-stage cp.async ring.
// 512 threads, 4x4 warp grid, 32x32 warp tiles -> 2 CTAs/SM = 32 warps/SM.
#define BM 128
#define BN 128
#define BKE 64
#define OPER 16384
#define STAGE (2*OPER)           // 32 KB
#define NSTAGE 3
#define SMEM_DYN (NSTAGE*STAGE)  // 98304 B
#define NTHREADS 512

#define M_PLAIN 0
#define M_GATE  1
#define M_SILU  2
#define M_PAIR  3   // interleaved value/gate cols -> v*sigm(g); bias/bias2 = bg0/bg0g
#define M_DUAL  4   // bn<HYP -> Ch(+bias, N=HYP); else -> Ch2(+bias2, N=HIDN)

__device__ __forceinline__ float sigm(float x) { return 1.f / (1.f + expf(-x)); }

__global__ __launch_bounds__(NTHREADS, 2)
void gemm_f16(const __half* __restrict__ A, const __half* __restrict__ W,
              const float* __restrict__ bias, const float* __restrict__ bias2,
              const __half* __restrict__ aux,
              int N, int K, int Nout, int mode,
              __half* __restrict__ Ch, __half* __restrict__ Ch2)
{
    extern __shared__ char dsmem[];
    const int tid = threadIdx.x, lane = tid & 31, wid = tid >> 5;
    const int warp_m = wid >> 2, warp_n = wid & 3;          // 4 x 4 warp grid
    const int bm = blockIdx.y * BM, bn = blockIdx.x * BN;
    const uint32_t sbase = smem_u32(dsmem);

    float acc[2][4][4];
#pragma unroll
    for (int i = 0; i < 2; i++)
#pragma unroll
        for (int j = 0; j < 4; j++)
#pragma unroll
            for (int q = 0; q < 4; q++) acc[i][j][q] = 0.f;

    // Precomputed ldmatrix base addresses; per-ks offset is addr ^ (ks*32)
    // (identity: ((2ks+ksX)^sw)*16 == ((ksX^sw)*16) ^ (ks*32), sw = row&7)
    uint32_t aadr[2], badr[2];
    {
        const uint32_t ksA = (lane >> 4) & 1;
        int rA = (lane & 7) + ((lane >> 3) & 1) * 8;
#pragma unroll
        for (int mf = 0; mf < 2; mf++) {
            int r = warp_m * 32 + mf * 16 + rA;
            aadr[mf] = (uint32_t)(r * 128) + (((ksA ^ (uint32_t)(r & 7)) << 4));
        }
        const uint32_t ksB = (lane >> 3) & 1;
        int rB = (lane & 7) + ((lane >> 4) & 1) * 8;
#pragma unroll
        for (int g = 0; g < 2; g++) {
            int r = warp_n * 32 + g * 16 + rB;
            badr[g] = (uint32_t)(r * 128) + (((ksB ^ (uint32_t)(r & 7)) << 4));
        }
    }

    const int spt = K / BKE;

    auto load_stage = [&](int k0, int buf) {
        uint32_t dA = sbase + (uint32_t)buf * STAGE;
        uint32_t dB = dA + OPER;
#pragma unroll
        for (int i = 0; i < 2; i++) {
            int c = i * NTHREADS + tid;       // 0..1023
            int r = c >> 3, seg = c & 7;
            uint32_t o = (uint32_t)(r * 128 + ((seg ^ (r & 7)) << 4));
            cp16(dA + o, A + (size_t)(bm + r) * K + k0 + seg * 8);
            cp16(dB + o, W + (size_t)(bn + r) * K + k0 + seg * 8);
        }
    };

    load_stage(0, 0);  cp_commit();
    load_stage(BKE, 1); cp_commit();

    for (int s = 0; s < spt; s++) {
        const int buf = s % NSTAGE;
        if (s < spt - 1) cp_wait<1>(); else cp_wait<0>();
        __syncthreads();
        if (s + 2 < spt) { load_stage((s + 2) * BKE, (s + 2) % NSTAGE); cp_commit(); }

        const uint32_t sA = sbase + (uint32_t)buf * STAGE;
        const uint32_t sB = sA + OPER;
#pragma unroll
        for (int ks = 0; ks < 4; ks++) {
            const uint32_t kx = (uint32_t)(ks << 5);
            uint32_t br[8], ar[2][4];
            ldm4(br,     sB + (badr[0] ^ kx));
            ldm4(br + 4, sB + (badr[1] ^ kx));
            ldm4(ar[0],  sA + (aadr[0] ^ kx));
            ldm4(ar[1],  sA + (aadr[1] ^ kx));
#pragma unroll
            for (int mf = 0; mf < 2; mf++)
#pragma unroll
                for (int nf = 0; nf < 4; nf++)
                    mma16816(acc[mf][nf], ar[mf], br + nf * 2);
        }
    }

    // ------------- fused epilogue -------------
    __half* outp = Ch;
    const float* biasp = bias;
    int Nloc = Nout, nbase = bn;
    if (mode == M_DUAL && bn >= HYP) {
        outp = Ch2; biasp = bias2; Nloc = HIDN; nbase = bn - HYP;
    }

    float2 bv[4];
#pragma unroll
    for (int nf = 0; nf < 4; nf++) {
        int nloc = nbase + warp_n * 32 + nf * 8 + (lane & 3) * 2;
        if (mode == M_PAIR) {
            bv[nf].x = bias[nloc >> 1];
            bv[nf].y = bias2[nloc >> 1];
        } else {
            bv[nf] = *(const float2*)&biasp[nloc];
        }
    }

#pragma unroll
    for (int mf = 0; mf < 2; mf++) {
#pragma unroll
        for (int h = 0; h < 2; h++) {
            const int row = bm + warp_m * 32 + mf * 16 + (lane >> 2) + h * 8;
#pragma unroll
            for (int nf = 0; nf < 4; nf++) {
                const int nloc = nbase + warp_n * 32 + nf * 8 + (lane & 3) * 2;
                float v0 = acc[mf][nf][h * 2 + 0] + bv[nf].x;
                float v1 = acc[mf][nf][h * 2 + 1] + bv[nf].y;
                if (mode == M_PAIR) {
                    outp[(size_t)row * Nout + (nloc >> 1)] = __float2half(v0 * sigm(v1));
                } else {
                    if (mode == M_GATE) {
                        __half2 g = *(const __half2*)&aux[(size_t)row * N + nloc];
                        v0 *= sigm(__half2float(g.x));
                        v1 *= sigm(__half2float(g.y));
                    } else if (mode == M_SILU) {
                        v0 *= sigm(v0); v1 *= sigm(v1);
                    }
                    __half2 o; o.x = __float2half(v0); o.y = __float2half(v1);
                    *(__half2*)&outp[(size_t)row * Nloc + nloc] = o;
                }
            }
        }
    }
}

// ---------------- mega conversion kernel (one launch) --------------------------
#define C0 (SEQ*INP)
#define C1 (C0 + HYP*INP)
#define C2 (C1 + HIDN*INP)
#define C3 (C2 + 2*HYP*HYP)
#define C4 (C3 + HYP*HYP)
#define C5 (C4 + HIDN*HYP)
#define CVT_THREADS ((C5)/4)

__device__ __forceinline__ void cvt4(const float* s, __half* d) {
    float4 v = *(const float4*)s;
    __half2 a; a.x = __float2half(v.x); a.y = __float2half(v.y);
    __half2 b; b.x = __float2half(v.z); b.y = __float2half(v.w);
    *(__half2*)d       = a;
    *(__half2*)(d + 2) = b;
}

__global__ void mega_cvt(const float* __restrict__ x,    const float* __restrict__ w_in,
                         const float* __restrict__ w2,   const float* __restrict__ wg0,
                         const float* __restrict__ wg0g, const float* __restrict__ wg_sh,
                         const float* __restrict__ w_h,
                         __half* __restrict__ xh, __half* __restrict__ w15,
                         __half* __restrict__ wI, __half* __restrict__ wshh,
                         __half* __restrict__ whh)
{
    int i = (blockIdx.x * blockDim.x + threadIdx.x) * 4;
    if (i < C0) {
        cvt4(x + i, xh + i);
    } else if (i < C1) {
        int j = i - C0; cvt4(w_in + j, w15 + j);
    } else if (i < C2) {
        int j = i - C1; cvt4(w2 + j, w15 + HYP*INP + j);
    } else if (i < C3) {
        int j = i - C2;
        int r = j >> 10, k = j & (HYP - 1);
        const float* s = (r & 1) ? wg0g : wg0;
        cvt4(s + ((size_t)(r >> 1) << 10) + k, wI + j);
    } else if (i < C4) {
        int j = i - C3; cvt4(wg_sh + j, wshh + j);
    } else if (i < C5) {
        int j = i - C4; cvt4(w_h + j, whh + j);
    }
}

// ---------------- rotated-frame relu scan (fp16 B) ----------------------------
__global__ void scan_pass1(const __half* __restrict__ B,
                           float* __restrict__ Ac, float* __restrict__ Bc)
{
    int t    = blockIdx.x * blockDim.x + threadIdx.x;
    int lane = t & (HIDN - 1);
    int chnk = t >> 12;
    float Aa = -1e30f, Ss = 0.f;
    int base = chnk * CHUNK;
#pragma unroll 8
    for (int i = 0; i < CHUNK; i++) {
        int row = base + i;
        float b = __half2float(B[(size_t)row * HIDN + ((lane + row) & (HIDN - 1))]);
        Aa = fmaxf(0.f, b + Aa);
        Ss += b;
    }
    Ac[t] = Aa; Bc[t] = Ss;
}

__global__ void scan_combine(const float* __restrict__ hidden,
                             const float* __restrict__ Ac, const float* __restrict__ Bc,
                             float* __restrict__ Gb)
{
    int lane = blockIdx.x * blockDim.x + threadIdx.x;
    float gv = hidden[(lane - 1) & (HIDN - 1)];
    Gb[lane] = gv;
    for (int c = 0; c < NCHUNK; c++) {
        gv = fmaxf(Ac[c * HIDN + lane], Bc[c * HIDN + lane] + gv);
        Gb[(c + 1) * HIDN + lane] = gv;
    }
}

__global__ void scan_pass2(const __half* __restrict__ B, const float* __restrict__ Gb,
                           float* __restrict__ out, float* __restrict__ hlast, int write_h)
{
    int t    = blockIdx.x * blockDim.x + threadIdx.x;
    int lane = t & (HIDN - 1);
    int chnk = t >> 12;
    float gv = Gb[chnk * HIDN + lane];
    int base = chnk * CHUNK;
#pragma unroll 4
    for (int i = 0; i < CHUNK; i++) {
        int row = base + i;
        int col = (lane + row) & (HIDN - 1);
        gv = fmaxf(0.f, __half2float(B[(size_t)row * HIDN + col]) + gv);
        out[(size_t)row * HIDN + col] = gv;
    }
    if (write_h && chnk == NCHUNK - 1)
        hlast[(lane - 1) & (HIDN - 1)] = gv;
}

// ---------------- launch ------------------------------------------------------
extern "C" void kernel_launch(void* const* d_in, const int* in_sizes, int n_in,
                              void* d_out, int out_size)
{
    const float* x      = (const float*)d_in[0];
    const float* hidden = (const float*)d_in[1];
    const float* w_in   = (const float*)d_in[2];
    const float* b_in   = (const float*)d_in[3];
    const float* wg0    = (const float*)d_in[4];
    const float* bg0    = (const float*)d_in[5];
    const float* wg0g   = (const float*)d_in[6];
    const float* bg0g   = (const float*)d_in[7];
    const float* wg_sh  = (const float*)d_in[8];
    const float* bg_sh  = (const float*)d_in[9];
    const float* w_h    = (const float*)d_in[10];
    const float* b_h    = (const float*)d_in[11];
    const float* w2     = (const float*)d_in[12];
    const float* b2     = (const float*)d_in[13];

    float* out   = (float*)d_out;
    float* hlast = out + (size_t)SEQ * HIDN;
    int write_h  = (out_size >= SEQ * HIDN + HIDN) ? 1 : 0;

    cudaFuncSetAttribute(gemm_f16, cudaFuncAttributeMaxDynamicSharedMemorySize, SMEM_DYN);

    __half *xh, *h1h, *h2h, *h3h, *Gh, *Bh, *w15, *wI, *wshh, *whh;
    float *Ac, *Bc, *Gb;
    cudaGetSymbolAddress((void**)&xh,  g_xh);
    cudaGetSymbolAddress((void**)&h1h, g_h1h);
    cudaGetSymbolAddress((void**)&h2h, g_h2h);
    cudaGetSymbolAddress((void**)&h3h, g_h3h);
    cudaGetSymbolAddress((void**)&Gh,  g_Gh);
    cudaGetSymbolAddress((void**)&Bh,  g_Bh);
    cudaGetSymbolAddress((void**)&w15,  g_w15);
    cudaGetSymbolAddress((void**)&wI,   g_wI);
    cudaGetSymbolAddress((void**)&wshh, g_wshh);
    cudaGetSymbolAddress((void**)&whh,  g_whh);
    cudaGetSymbolAddress((void**)&Ac, g_Ac);
    cudaGetSymbolAddress((void**)&Bc, g_Bc);
    cudaGetSymbolAddress((void**)&Gb, g_Gb);

    mega_cvt<<<(CVT_THREADS + 255)/256, 256>>>(x, w_in, w2, wg0, wg0g, wg_sh, w_h,
                                               xh, w15, wI, wshh, whh);

    const dim3 gDual((HYP + HIDN) / BN, SEQ / BM);   // 40 x 64
    const dim3 gPair(2*HYP / BN,        SEQ / BM);   // 16 x 64
    const dim3 gHyp (HYP / BN,          SEQ / BM);   //  8 x 64
    const dim3 gHid (HIDN / BN,         SEQ / BM);   // 32 x 64

    // [h1 ; G] = x @ [w_in ; w2]^T + [b_in ; b2]
    gemm_f16<<<gDual, NTHREADS, SMEM_DYN>>>(xh, w15, b_in, b2, nullptr,
                                            HYP + HIDN, INP, HYP, M_DUAL, h1h, Gh);
    // h2 = (h1 @ wg0^T + bg0) * sigmoid(h1 @ wg0g^T + bg0g)
    gemm_f16<<<gPair, NTHREADS, SMEM_DYN>>>(h1h, wI, bg0, bg0g, nullptr,
                                            2*HYP, HYP, HYP, M_PAIR, h2h, nullptr);
    // h3 = silu(h2 @ wg_sh^T + bg_sh)
    gemm_f16<<<gHyp, NTHREADS, SMEM_DYN>>>(h2h, wshh, bg_sh, nullptr, nullptr,
                                           HYP, HYP, HYP, M_SILU, h3h, nullptr);
    // B = (h3 @ w_h^T + b_h) * sigmoid(G)
    gemm_f16<<<gHid, NTHREADS, SMEM_DYN>>>(h3h, whh, b_h, nullptr, Gh,
                                           HIDN, HYP, HIDN, M_GATE, Bh, nullptr);

    // chunked rotated-frame scan
    scan_pass1 <<<NCHUNK*HIDN/256, 256>>>(Bh, Ac, Bc);
    scan_combine<<<HIDN/256, 256>>>(hidden, Ac, Bc, Gb);
    scan_pass2 <<<NCHUNK*HIDN/256, 256>>>(Bh, Gb, out, hlast, write_h);
}

// round 12
// speedup vs baseline: 1.1165x; 1.1165x over previous
#include <cuda_runtime.h>
#include <cuda_fp16.h>
#include <stdint.h>
#include <math.h>

#define SEQ   8192
#define INP   512
#define HYP   1024
#define HIDN  4096
#define CHUNK 128
#define NCHUNK (SEQ/CHUNK)   // 64

// ---------------- scratch (static __device__, no allocations) ----------------
__device__ __half g_xh  [SEQ*INP];
__device__ __half g_h1h [SEQ*HYP];
__device__ __half g_h2h [SEQ*HYP];
__device__ __half g_h3h [SEQ*HYP];
__device__ __half g_Gh  [SEQ*HIDN];
__device__ __half g_Bh  [SEQ*HIDN];
__device__ __half g_winh[HYP*INP];
__device__ __half g_wI  [2*HYP*HYP];         // interleaved wg0/wg0g
__device__ __half g_wshh[HYP*HYP];
__device__ __half g_whh [HIDN*HYP];
__device__ __half g_w2h [HIDN*INP];
__device__ float g_Ac[NCHUNK*HIDN];
__device__ float g_Bc[NCHUNK*HIDN];
__device__ float g_Gb[(NCHUNK+1)*HIDN];

// ---------------- PTX helpers (sm_100-portable only) --------------------------
__device__ __forceinline__ uint32_t smem_u32(const void* p) {
    uint32_t a;
    asm("{ .reg .u64 t; cvta.to.shared.u64 t, %1; cvt.u32.u64 %0, t; }" : "=r"(a) : "l"(p));
    return a;
}
__device__ __forceinline__ void cp16(uint32_t dst, const void* src) {
    asm volatile("cp.async.cg.shared.global [%0], [%1], 16;" :: "r"(dst), "l"(src));
}
__device__ __forceinline__ void cp_commit() { asm volatile("cp.async.commit_group;"); }
template <int N> __device__ __forceinline__ void cp_wait() {
    asm volatile("cp.async.wait_group %0;" :: "n"(N));
}
__device__ __forceinline__ void ldm4(uint32_t* r, uint32_t addr) {
    asm volatile("ldmatrix.sync.aligned.m8n8.x4.shared.b16 {%0,%1,%2,%3}, [%4];"
                 : "=r"(r[0]), "=r"(r[1]), "=r"(r[2]), "=r"(r[3]) : "r"(addr));
}
__device__ __forceinline__ void mma16816(float* d, const uint32_t* a, const uint32_t* b) {
    asm volatile(
        "mma.sync.aligned.m16n8k16.row.col.f32.f16.f16.f32 "
        "{%0,%1,%2,%3}, {%4,%5,%6,%7}, {%8,%9}, {%0,%1,%2,%3};"
        : "+f"(d[0]), "+f"(d[1]), "+f"(d[2]), "+f"(d[3])
        : "r"(a[0]), "r"(a[1]), "r"(a[2]), "r"(a[3]), "r"(b[0]), "r"(b[1]));
}

// ---------------- fp16 GEMM (R8 config): 256 thr, 2x4 warps, 64x32 tiles ------
#define BM 128
#define BN 128
#define BKE 64
#define OPER 16384
#define STAGE (2*OPER)           // 32 KB
#define NSTAGE 3
#define SMEM_DYN (NSTAGE*STAGE)  // 98304 B
#define NTHREADS 256

#define M_PLAIN 0
#define M_GATE  1
#define M_SILU  2
#define M_PAIR  3   // interleaved value/gate cols -> v*sigm(g); bias/bias2 = bg0/bg0g

__device__ __forceinline__ float sigm(float x) { return 1.f / (1.f + expf(-x)); }

__global__ __launch_bounds__(NTHREADS, 2)
void gemm_f16(const __half* __restrict__ A, const __half* __restrict__ W,
              const float* __restrict__ bias, const float* __restrict__ bias2,
              const __half* __restrict__ aux,
              int N, int K, int Nout, int mode, __half* __restrict__ Ch)
{
    extern __shared__ char dsmem[];
    const int tid = threadIdx.x, lane = tid & 31, wid = tid >> 5;
    const int warp_m = wid >> 2, warp_n = wid & 3;          // 2 x 4 warp grid
    const int bm = blockIdx.y * BM, bn = blockIdx.x * BN;
    const uint32_t sbase = smem_u32(dsmem);

    float acc[4][4][4];
#pragma unroll
    for (int i = 0; i < 4; i++)
#pragma unroll
        for (int j = 0; j < 4; j++)
#pragma unroll
            for (int q = 0; q < 4; q++) acc[i][j][q] = 0.f;

    // ldmatrix base addresses; per-ks offset = addr ^ (ks*32)
    uint32_t aadr[4], badr[2];
    {
        const uint32_t ksA = (lane >> 4) & 1;
        int rA = (lane & 7) + ((lane >> 3) & 1) * 8;
#pragma unroll
        for (int mf = 0; mf < 4; mf++) {
            int r = warp_m * 64 + mf * 16 + rA;
            aadr[mf] = (uint32_t)(r * 128) + ((ksA ^ (uint32_t)(r & 7)) << 4);
        }
        const uint32_t ksB = (lane >> 3) & 1;
        int rB = (lane & 7) + ((lane >> 4) & 1) * 8;
#pragma unroll
        for (int g = 0; g < 2; g++) {
            int r = warp_n * 32 + g * 16 + rB;
            badr[g] = (uint32_t)(r * 128) + ((ksB ^ (uint32_t)(r & 7)) << 4);
        }
    }

    const int spt = K / BKE;

    auto load_stage = [&](int k0, int buf) {
        uint32_t dA = sbase + (uint32_t)buf * STAGE;
        uint32_t dB = dA + OPER;
#pragma unroll
        for (int i = 0; i < 4; i++) {
            int c = i * NTHREADS + tid;       // 0..1023
            int r = c >> 3, seg = c & 7;
            uint32_t o = (uint32_t)(r * 128 + ((seg ^ (r & 7)) << 4));
            cp16(dA + o, A + (size_t)(bm + r) * K + k0 + seg * 8);
            cp16(dB + o, W + (size_t)(bn + r) * K + k0 + seg * 8);
        }
    };

    load_stage(0, 0);  cp_commit();
    load_stage(BKE, 1); cp_commit();

    for (int s = 0; s < spt; s++) {
        const int buf = s % NSTAGE;
        if (s < spt - 1) cp_wait<1>(); else cp_wait<0>();
        __syncthreads();
        if (s + 2 < spt) { load_stage((s + 2) * BKE, (s + 2) % NSTAGE); cp_commit(); }

        const uint32_t sA = sbase + (uint32_t)buf * STAGE;
        const uint32_t sB = sA + OPER;
#pragma unroll
        for (int ks = 0; ks < 4; ks++) {
            const uint32_t kx = (uint32_t)(ks << 5);
            uint32_t br[8];
            ldm4(br,     sB + (badr[0] ^ kx));
            ldm4(br + 4, sB + (badr[1] ^ kx));
#pragma unroll
            for (int mf = 0; mf < 4; mf++) {
                uint32_t ar[4];
                ldm4(ar, sA + (aadr[mf] ^ kx));
#pragma unroll
                for (int nf = 0; nf < 4; nf++)
                    mma16816(acc[mf][nf], ar, br + nf * 2);
            }
        }
    }

    // ------------- fused epilogue -------------
    float2 bv[4];
#pragma unroll
    for (int nf = 0; nf < 4; nf++) {
        int nloc = bn + warp_n * 32 + nf * 8 + (lane & 3) * 2;
        if (mode == M_PAIR) {
            bv[nf].x = bias[nloc >> 1];
            bv[nf].y = bias2[nloc >> 1];
        } else {
            bv[nf] = *(const float2*)&bias[nloc];
        }
    }

#pragma unroll
    for (int mf = 0; mf < 4; mf++) {
#pragma unroll
        for (int h = 0; h < 2; h++) {
            const int row = bm + warp_m * 64 + mf * 16 + (lane >> 2) + h * 8;
#pragma unroll
            for (int nf = 0; nf < 4; nf++) {
                const int nloc = bn + warp_n * 32 + nf * 8 + (lane & 3) * 2;
                float v0 = acc[mf][nf][h * 2 + 0] + bv[nf].x;
                float v1 = acc[mf][nf][h * 2 + 1] + bv[nf].y;
                if (mode == M_PAIR) {
                    Ch[(size_t)row * Nout + (nloc >> 1)] = __float2half(v0 * sigm(v1));
                } else {
                    if (mode == M_GATE) {
                        __half2 g = *(const __half2*)&aux[(size_t)row * N + nloc];
                        v0 *= sigm(__half2float(g.x));
                        v1 *= sigm(__half2float(g.y));
                    } else if (mode == M_SILU) {
                        v0 *= sigm(v0); v1 *= sigm(v1);
                    }
                    __half2 o; o.x = __float2half(v0); o.y = __float2half(v1);
                    *(__half2*)&Ch[(size_t)row * Nout + nloc] = o;
                }
            }
        }
    }
}

// ---------------- conversion kernels (split for overlap) -----------------------
__device__ __forceinline__ void cvt4(const float* s, __half* d) {
    float4 v = *(const float4*)s;
    __half2 a; a.x = __float2half(v.x); a.y = __float2half(v.y);
    __half2 b; b.x = __float2half(v.z); b.y = __float2half(v.w);
    *(__half2*)d       = a;
    *(__half2*)(d + 2) = b;
}

// A-side: x + w_in (needed by h1)
#define A0 (SEQ*INP)
#define A1 (A0 + HYP*INP)
__global__ void cvtA(const float* __restrict__ x, const float* __restrict__ w_in,
                     __half* __restrict__ xh, __half* __restrict__ winh)
{
    int i = (blockIdx.x * blockDim.x + threadIdx.x) * 4;
    if (i < A0)      cvt4(x + i, xh + i);
    else if (i < A1) { int j = i - A0; cvt4(w_in + j, winh + j); }
}

// B-side: wI interleave + wshh + whh + w2h (needed by pair/h3/B/G)
#define B0 (2*HYP*HYP)
#define B1 (B0 + HYP*HYP)
#define B2 (B1 + HIDN*HYP)
#define B3 (B2 + HIDN*INP)
__global__ void cvtB(const float* __restrict__ wg0, const float* __restrict__ wg0g,
                     const float* __restrict__ wg_sh, const float* __restrict__ w_h,
                     const float* __restrict__ w2,
                     __half* __restrict__ wI, __half* __restrict__ wshh,
                     __half* __restrict__ whh, __half* __restrict__ w2h)
{
    int i = (blockIdx.x * blockDim.x + threadIdx.x) * 4;
    if (i < B0) {
        int r = i >> 10, k = i & (HYP - 1);
        const float* s = (r & 1) ? wg0g : wg0;
        cvt4(s + ((size_t)(r >> 1) << 10) + k, wI + i);
    } else if (i < B1) { int j = i - B0; cvt4(wg_sh + j, wshh + j); }
    else if (i < B2)   { int j = i - B1; cvt4(w_h + j, whh + j); }
    else if (i < B3)   { int j = i - B2; cvt4(w2 + j, w2h + j); }
}

// ---------------- rotated-frame relu scan (fp16 B) ----------------------------
__global__ void scan_pass1(const __half* __restrict__ B,
                           float* __restrict__ Ac, float* __restrict__ Bc)
{
    int t    = blockIdx.x * blockDim.x + threadIdx.x;
    int lane = t & (HIDN - 1);
    int chnk = t >> 12;
    float Aa = -1e30f, Ss = 0.f;
    int base = chnk * CHUNK;
#pragma unroll 8
    for (int i = 0; i < CHUNK; i++) {
        int row = base + i;
        float b = __half2float(B[(size_t)row * HIDN + ((lane + row) & (HIDN - 1))]);
        Aa = fmaxf(0.f, b + Aa);
        Ss += b;
    }
    Ac[t] = Aa; Bc[t] = Ss;
}

__global__ void scan_combine(const float* __restrict__ hidden,
                             const float* __restrict__ Ac, const float* __restrict__ Bc,
                             float* __restrict__ Gb)
{
    int lane = blockIdx.x * blockDim.x + threadIdx.x;
    float gv = hidden[(lane - 1) & (HIDN - 1)];
    Gb[lane] = gv;
    for (int c = 0; c < NCHUNK; c++) {
        gv = fmaxf(Ac[c * HIDN + lane], Bc[c * HIDN + lane] + gv);
        Gb[(c + 1) * HIDN + lane] = gv;
    }
}

__global__ void scan_pass2(const __half* __restrict__ B, const float* __restrict__ Gb,
                           float* __restrict__ out, float* __restrict__ hlast, int write_h)
{
    int t    = blockIdx.x * blockDim.x + threadIdx.x;
    int lane = t & (HIDN - 1);
    int chnk = t >> 12;
    float gv = Gb[chnk * HIDN + lane];
    int base = chnk * CHUNK;
#pragma unroll 4
    for (int i = 0; i < CHUNK; i++) {
        int row = base + i;
        int col = (lane + row) & (HIDN - 1);
        gv = fmaxf(0.f, __half2float(B[(size_t)row * HIDN + col]) + gv);
        out[(size_t)row * HIDN + col] = gv;
    }
    if (write_h && chnk == NCHUNK - 1)
        hlast[(lane - 1) & (HIDN - 1)] = gv;
}

// ---------------- launch ------------------------------------------------------
extern "C" void kernel_launch(void* const* d_in, const int* in_sizes, int n_in,
                              void* d_out, int out_size)
{
    const float* x      = (const float*)d_in[0];
    const float* hidden = (const float*)d_in[1];
    const float* w_in   = (const float*)d_in[2];
    const float* b_in   = (const float*)d_in[3];
    const float* wg0    = (const float*)d_in[4];
    const float* bg0    = (const float*)d_in[5];
    const float* wg0g   = (const float*)d_in[6];
    const float* bg0g   = (const float*)d_in[7];
    const float* wg_sh  = (const float*)d_in[8];
    const float* bg_sh  = (const float*)d_in[9];
    const float* w_h    = (const float*)d_in[10];
    const float* b_h    = (const float*)d_in[11];
    const float* w2     = (const float*)d_in[12];
    const float* b2     = (const float*)d_in[13];

    float* out   = (float*)d_out;
    float* hlast = out + (size_t)SEQ * HIDN;
    int write_h  = (out_size >= SEQ * HIDN + HIDN) ? 1 : 0;

    cudaFuncSetAttribute(gemm_f16, cudaFuncAttributeMaxDynamicSharedMemorySize, SMEM_DYN);

    // Side stream + events: created once on the first (correctness) call, so the
    // capture call performs no resource creation. Same work on every call.
    static cudaStream_t s2 = nullptr;
    static cudaEvent_t evRoot = nullptr, evB = nullptr, evG = nullptr;
    if (s2 == nullptr) {
        cudaStreamCreateWithFlags(&s2, cudaStreamNonBlocking);
        cudaEventCreateWithFlags(&evRoot, cudaEventDisableTiming);
        cudaEventCreateWithFlags(&evB,    cudaEventDisableTiming);
        cudaEventCreateWithFlags(&evG,    cudaEventDisableTiming);
    }

    __half *xh, *h1h, *h2h, *h3h, *Gh, *Bh, *winh, *wI, *wshh, *whh, *w2h;
    float *Ac, *Bc, *Gb;
    cudaGetSymbolAddress((void**)&xh,  g_xh);
    cudaGetSymbolAddress((void**)&h1h, g_h1h);
    cudaGetSymbolAddress((void**)&h2h, g_h2h);
    cudaGetSymbolAddress((void**)&h3h, g_h3h);
    cudaGetSymbolAddress((void**)&Gh,  g_Gh);
    cudaGetSymbolAddress((void**)&Bh,  g_Bh);
    cudaGetSymbolAddress((void**)&winh, g_winh);
    cudaGetSymbolAddress((void**)&wI,   g_wI);
    cudaGetSymbolAddress((void**)&wshh, g_wshh);
    cudaGetSymbolAddress((void**)&whh,  g_whh);
    cudaGetSymbolAddress((void**)&w2h,  g_w2h);
    cudaGetSymbolAddress((void**)&Ac, g_Ac);
    cudaGetSymbolAddress((void**)&Bc, g_Bc);
    cudaGetSymbolAddress((void**)&Gb, g_Gb);

    const dim3 gHyp (HYP / BN,   SEQ / BM);   //  8 x 64
    const dim3 gPair(2*HYP / BN, SEQ / BM);   // 16 x 64
    const dim3 gHid (HIDN / BN,  SEQ / BM);   // 32 x 64

    // ---- fork side stream from main stream ----
    cudaEventRecord(evRoot, 0);
    cudaStreamWaitEvent(s2, evRoot, 0);

    // main: convert x + w_in, then h1 GEMM
    cvtA<<<(A1/4 + 255)/256, 256>>>(x, w_in, xh, winh);
    // side: convert remaining weights, then G GEMM (needs xh -> wait via evB? no:
    // xh is produced by cvtA on main; side must wait for it before G)
    cvtB<<<(B3/4 + 255)/256, 256, 0, s2>>>(wg0, wg0g, wg_sh, w_h, w2,
                                           wI, wshh, whh, w2h);
    cudaEventRecord(evB, s2);          // weights (wI/wshh/whh) ready

    // main: h1 = x @ w_in^T + b_in
    gemm_f16<<<gHyp, NTHREADS, SMEM_DYN>>>(xh, winh, b_in, nullptr, nullptr,
                                           HYP, INP, HYP, M_PLAIN, h1h);
    cudaEventRecord(evRoot, 0);        // xh (and h1) ready for side stream
    cudaStreamWaitEvent(s2, evRoot, 0);

    // side: G = x @ w2^T + b2  (overlaps pair + h3 on main)
    gemm_f16<<<gHid, NTHREADS, SMEM_DYN, s2>>>(xh, w2h, b2, nullptr, nullptr,
                                               HIDN, INP, HIDN, M_PLAIN, Gh);
    cudaEventRecord(evG, s2);

    // main: wait for wI/wshh, then pair + h3
    cudaStreamWaitEvent(0, evB, 0);
    gemm_f16<<<gPair, NTHREADS, SMEM_DYN>>>(h1h, wI, bg0, bg0g, nullptr,
                                            2*HYP, HYP, HYP, M_PAIR, h2h);
    gemm_f16<<<gHyp, NTHREADS, SMEM_DYN>>>(h2h, wshh, bg_sh, nullptr, nullptr,
                                           HYP, HYP, HYP, M_SILU, h3h);

    // join: B = (h3 @ w_h^T + b_h) * sigmoid(G)
    cudaStreamWaitEvent(0, evG, 0);
    gemm_f16<<<gHid, NTHREADS, SMEM_DYN>>>(h3h, whh, b_h, nullptr, Gh,
                                           HIDN, HYP, HIDN, M_GATE, Bh);

    // chunked rotated-frame scan
    scan_pass1 <<<NCHUNK*HIDN/256, 256>>>(Bh, Ac, Bc);
    scan_combine<<<HIDN/256, 256>>>(hidden, Ac, Bc, Gb);
    scan_pass2 <<<NCHUNK*HIDN/256, 256>>>(Bh, Gb, out, hlast, write_h);
}

// round 13
// speedup vs baseline: 1.1439x; 1.0245x over previous
#include <cuda_runtime.h>
#include <cuda_fp16.h>
#include <stdint.h>
#include <math.h>

#define SEQ   8192
#define INP   512
#define HYP   1024
#define HIDN  4096
#define CHUNK 128
#define NCHUNK (SEQ/CHUNK)   // 64
#define HSEQ  (SEQ/2)        // 4096 rows per half-pipeline

// ---------------- scratch (static __device__, no allocations) ----------------
__device__ __half g_xh  [SEQ*INP];
__device__ __half g_h1h [SEQ*HYP];
__device__ __half g_h2h [SEQ*HYP];
__device__ __half g_h3h [SEQ*HYP];
__device__ __half g_Gh  [SEQ*HIDN];
__device__ __half g_Bh  [SEQ*HIDN];
__device__ __half g_winh[HYP*INP];
__device__ __half g_wI  [2*HYP*HYP];         // interleaved wg0/wg0g
__device__ __half g_wshh[HYP*HYP];
__device__ __half g_whh [HIDN*HYP];
__device__ __half g_w2h [HIDN*INP];
__device__ float g_Ac[NCHUNK*HIDN];
__device__ float g_Bc[NCHUNK*HIDN];
__device__ float g_Gb[(NCHUNK+1)*HIDN];

// ---------------- PTX helpers (sm_100-portable only) --------------------------
__device__ __forceinline__ uint32_t smem_u32(const void* p) {
    uint32_t a;
    asm("{ .reg .u64 t; cvta.to.shared.u64 t, %1; cvt.u32.u64 %0, t; }" : "=r"(a) : "l"(p));
    return a;
}
__device__ __forceinline__ void cp16(uint32_t dst, const void* src) {
    asm volatile("cp.async.cg.shared.global [%0], [%1], 16;" :: "r"(dst), "l"(src));
}
__device__ __forceinline__ void cp_commit() { asm volatile("cp.async.commit_group;"); }
template <int N> __device__ __forceinline__ void cp_wait() {
    asm volatile("cp.async.wait_group %0;" :: "n"(N));
}
__device__ __forceinline__ void ldm4(uint32_t* r, uint32_t addr) {
    asm volatile("ldmatrix.sync.aligned.m8n8.x4.shared.b16 {%0,%1,%2,%3}, [%4];"
                 : "=r"(r[0]), "=r"(r[1]), "=r"(r[2]), "=r"(r[3]) : "r"(addr));
}
__device__ __forceinline__ void mma16816(float* d, const uint32_t* a, const uint32_t* b) {
    asm volatile(
        "mma.sync.aligned.m16n8k16.row.col.f32.f16.f16.f32 "
        "{%0,%1,%2,%3}, {%4,%5,%6,%7}, {%8,%9}, {%0,%1,%2,%3};"
        : "+f"(d[0]), "+f"(d[1]), "+f"(d[2]), "+f"(d[3])
        : "r"(a[0]), "r"(a[1]), "r"(a[2]), "r"(a[3]), "r"(b[0]), "r"(b[1]));
}

// ---------------- fp16 GEMM (R8 config): 256 thr, 2x4 warps, 64x32 tiles ------
#define BM 128
#define BN 128
#define BKE 64
#define OPER 16384
#define STAGE (2*OPER)           // 32 KB
#define NSTAGE 3
#define SMEM_DYN (NSTAGE*STAGE)  // 98304 B
#define NTHREADS 256

#define M_PLAIN 0
#define M_GATE  1
#define M_SILU  2
#define M_PAIR  3   // interleaved value/gate cols -> v*sigm(g); bias/bias2 = bg0/bg0g

__device__ __forceinline__ float sigm(float x) { return 1.f / (1.f + expf(-x)); }

__global__ __launch_bounds__(NTHREADS, 2)
void gemm_f16(const __half* __restrict__ A, const __half* __restrict__ W,
              const float* __restrict__ bias, const float* __restrict__ bias2,
              const __half* __restrict__ aux,
              int N, int K, int Nout, int mode, __half* __restrict__ Ch)
{
    extern __shared__ char dsmem[];
    const int tid = threadIdx.x, lane = tid & 31, wid = tid >> 5;
    const int warp_m = wid >> 2, warp_n = wid & 3;          // 2 x 4 warp grid
    const int bm = blockIdx.y * BM, bn = blockIdx.x * BN;
    const uint32_t sbase = smem_u32(dsmem);

    float acc[4][4][4];
#pragma unroll
    for (int i = 0; i < 4; i++)
#pragma unroll
        for (int j = 0; j < 4; j++)
#pragma unroll
            for (int q = 0; q < 4; q++) acc[i][j][q] = 0.f;

    uint32_t aadr[4], badr[2];
    {
        const uint32_t ksA = (lane >> 4) & 1;
        int rA = (lane & 7) + ((lane >> 3) & 1) * 8;
#pragma unroll
        for (int mf = 0; mf < 4; mf++) {
            int r = warp_m * 64 + mf * 16 + rA;
            aadr[mf] = (uint32_t)(r * 128) + ((ksA ^ (uint32_t)(r & 7)) << 4);
        }
        const uint32_t ksB = (lane >> 3) & 1;
        int rB = (lane & 7) + ((lane >> 4) & 1) * 8;
#pragma unroll
        for (int g = 0; g < 2; g++) {
            int r = warp_n * 32 + g * 16 + rB;
            badr[g] = (uint32_t)(r * 128) + ((ksB ^ (uint32_t)(r & 7)) << 4);
        }
    }

    const int spt = K / BKE;

    auto load_stage = [&](int k0, int buf) {
        uint32_t dA = sbase + (uint32_t)buf * STAGE;
        uint32_t dB = dA + OPER;
#pragma unroll
        for (int i = 0; i < 4; i++) {
            int c = i * NTHREADS + tid;
            int r = c >> 3, seg = c & 7;
            uint32_t o = (uint32_t)(r * 128 + ((seg ^ (r & 7)) << 4));
            cp16(dA + o, A + (size_t)(bm + r) * K + k0 + seg * 8);
            cp16(dB + o, W + (size_t)(bn + r) * K + k0 + seg * 8);
        }
    };

    load_stage(0, 0);  cp_commit();
    load_stage(BKE, 1); cp_commit();

    for (int s = 0; s < spt; s++) {
        const int buf = s % NSTAGE;
        if (s < spt - 1) cp_wait<1>(); else cp_wait<0>();
        __syncthreads();
        if (s + 2 < spt) { load_stage((s + 2) * BKE, (s + 2) % NSTAGE); cp_commit(); }

        const uint32_t sA = sbase + (uint32_t)buf * STAGE;
        const uint32_t sB = sA + OPER;
#pragma unroll
        for (int ks = 0; ks < 4; ks++) {
            const uint32_t kx = (uint32_t)(ks << 5);
            uint32_t br[8];
            ldm4(br,     sB + (badr[0] ^ kx));
            ldm4(br + 4, sB + (badr[1] ^ kx));
#pragma unroll
            for (int mf = 0; mf < 4; mf++) {
                uint32_t ar[4];
                ldm4(ar, sA + (aadr[mf] ^ kx));
#pragma unroll
                for (int nf = 0; nf < 4; nf++)
                    mma16816(acc[mf][nf], ar, br + nf * 2);
            }
        }
    }

    // ------------- fused epilogue -------------
    float2 bv[4];
#pragma unroll
    for (int nf = 0; nf < 4; nf++) {
        int nloc = bn + warp_n * 32 + nf * 8 + (lane & 3) * 2;
        if (mode == M_PAIR) {
            bv[nf].x = bias[nloc >> 1];
            bv[nf].y = bias2[nloc >> 1];
        } else {
            bv[nf] = *(const float2*)&bias[nloc];
        }
    }

#pragma unroll
    for (int mf = 0; mf < 4; mf++) {
#pragma unroll
        for (int h = 0; h < 2; h++) {
            const int row = bm + warp_m * 64 + mf * 16 + (lane >> 2) + h * 8;
#pragma unroll
            for (int nf = 0; nf < 4; nf++) {
                const int nloc = bn + warp_n * 32 + nf * 8 + (lane & 3) * 2;
                float v0 = acc[mf][nf][h * 2 + 0] + bv[nf].x;
                float v1 = acc[mf][nf][h * 2 + 1] + bv[nf].y;
                if (mode == M_PAIR) {
                    Ch[(size_t)row * Nout + (nloc >> 1)] = __float2half(v0 * sigm(v1));
                } else {
                    if (mode == M_GATE) {
                        __half2 g = *(const __half2*)&aux[(size_t)row * N + nloc];
                        v0 *= sigm(__half2float(g.x));
                        v1 *= sigm(__half2float(g.y));
                    } else if (mode == M_SILU) {
                        v0 *= sigm(v0); v1 *= sigm(v1);
                    }
                    __half2 o; o.x = __float2half(v0); o.y = __float2half(v1);
                    *(__half2*)&Ch[(size_t)row * Nout + nloc] = o;
                }
            }
        }
    }
}

// ---------------- conversion kernels (split for overlap) -----------------------
__device__ __forceinline__ void cvt4(const float* s, __half* d) {
    float4 v = *(const float4*)s;
    __half2 a; a.x = __float2half(v.x); a.y = __float2half(v.y);
    __half2 b; b.x = __float2half(v.z); b.y = __float2half(v.w);
    *(__half2*)d       = a;
    *(__half2*)(d + 2) = b;
}

#define A0 (SEQ*INP)
#define A1 (A0 + HYP*INP)
__global__ void cvtA(const float* __restrict__ x, const float* __restrict__ w_in,
                     __half* __restrict__ xh, __half* __restrict__ winh)
{
    int i = (blockIdx.x * blockDim.x + threadIdx.x) * 4;
    if (i < A0)      cvt4(x + i, xh + i);
    else if (i < A1) { int j = i - A0; cvt4(w_in + j, winh + j); }
}

#define B0 (2*HYP*HYP)
#define B1 (B0 + HYP*HYP)
#define B2 (B1 + HIDN*HYP)
#define B3 (B2 + HIDN*INP)
__global__ void cvtB(const float* __restrict__ wg0, const float* __restrict__ wg0g,
                     const float* __restrict__ wg_sh, const float* __restrict__ w_h,
                     const float* __restrict__ w2,
                     __half* __restrict__ wI, __half* __restrict__ wshh,
                     __half* __restrict__ whh, __half* __restrict__ w2h)
{
    int i = (blockIdx.x * blockDim.x + threadIdx.x) * 4;
    if (i < B0) {
        int r = i >> 10, k = i & (HYP - 1);
        const float* s = (r & 1) ? wg0g : wg0;
        cvt4(s + ((size_t)(r >> 1) << 10) + k, wI + i);
    } else if (i < B1) { int j = i - B0; cvt4(wg_sh + j, wshh + j); }
    else if (i < B2)   { int j = i - B1; cvt4(w_h + j, whh + j); }
    else if (i < B3)   { int j = i - B2; cvt4(w2 + j, w2h + j); }
}

// ---------------- rotated-frame relu scan (fp16 B, half-split pass1) ----------
__global__ void scan_pass1(const __half* __restrict__ B,
                           float* __restrict__ Ac, float* __restrict__ Bc,
                           int chunk_base)
{
    int t     = blockIdx.x * blockDim.x + threadIdx.x;   // [0, 32*HIDN)
    int lane  = t & (HIDN - 1);
    int chnk  = chunk_base + (t >> 12);
    float Aa = -1e30f, Ss = 0.f;
    int base = chnk * CHUNK;
#pragma unroll 8
    for (int i = 0; i < CHUNK; i++) {
        int row = base + i;
        float b = __half2float(B[(size_t)row * HIDN + ((lane + row) & (HIDN - 1))]);
        Aa = fmaxf(0.f, b + Aa);
        Ss += b;
    }
    Ac[chnk * HIDN + lane] = Aa;
    Bc[chnk * HIDN + lane] = Ss;
}

__global__ void scan_combine(const float* __restrict__ hidden,
                             const float* __restrict__ Ac, const float* __restrict__ Bc,
                             float* __restrict__ Gb)
{
    int lane = blockIdx.x * blockDim.x + threadIdx.x;
    float gv = hidden[(lane - 1) & (HIDN - 1)];
    Gb[lane] = gv;
    for (int c = 0; c < NCHUNK; c++) {
        gv = fmaxf(Ac[c * HIDN + lane], Bc[c * HIDN + lane] + gv);
        Gb[(c + 1) * HIDN + lane] = gv;
    }
}

__global__ void scan_pass2(const __half* __restrict__ B, const float* __restrict__ Gb,
                           float* __restrict__ out, float* __restrict__ hlast, int write_h)
{
    int t    = blockIdx.x * blockDim.x + threadIdx.x;
    int lane = t & (HIDN - 1);
    int chnk = t >> 12;
    float gv = Gb[chnk * HIDN + lane];
    int base = chnk * CHUNK;
#pragma unroll 4
    for (int i = 0; i < CHUNK; i++) {
        int row = base + i;
        int col = (lane + row) & (HIDN - 1);
        gv = fmaxf(0.f, __half2float(B[(size_t)row * HIDN + col]) + gv);
        out[(size_t)row * HIDN + col] = gv;
    }
    if (write_h && chnk == NCHUNK - 1)
        hlast[(lane - 1) & (HIDN - 1)] = gv;
}

// ---------------- launch ------------------------------------------------------
extern "C" void kernel_launch(void* const* d_in, const int* in_sizes, int n_in,
                              void* d_out, int out_size)
{
    const float* x      = (const float*)d_in[0];
    const float* hidden = (const float*)d_in[1];
    const float* w_in   = (const float*)d_in[2];
    const float* b_in   = (const float*)d_in[3];
    const float* wg0    = (const float*)d_in[4];
    const float* bg0    = (const float*)d_in[5];
    const float* wg0g   = (const float*)d_in[6];
    const float* bg0g   = (const float*)d_in[7];
    const float* wg_sh  = (const float*)d_in[8];
    const float* bg_sh  = (const float*)d_in[9];
    const float* w_h    = (const float*)d_in[10];
    const float* b_h    = (const float*)d_in[11];
    const float* w2     = (const float*)d_in[12];
    const float* b2     = (const float*)d_in[13];

    float* out   = (float*)d_out;
    float* hlast = out + (size_t)SEQ * HIDN;
    int write_h  = (out_size >= SEQ * HIDN + HIDN) ? 1 : 0;

    cudaFuncSetAttribute(gemm_f16, cudaFuncAttributeMaxDynamicSharedMemorySize, SMEM_DYN);

    // Side stream + events: created once on the first (correctness) call.
    static cudaStream_t s2 = nullptr;
    static cudaEvent_t evRoot = nullptr, evX = nullptr, evW = nullptr, evHalf = nullptr;
    if (s2 == nullptr) {
        cudaStreamCreateWithFlags(&s2, cudaStreamNonBlocking);
        cudaEventCreateWithFlags(&evRoot, cudaEventDisableTiming);
        cudaEventCreateWithFlags(&evX,    cudaEventDisableTiming);
        cudaEventCreateWithFlags(&evW,    cudaEventDisableTiming);
        cudaEventCreateWithFlags(&evHalf, cudaEventDisableTiming);
    }

    __half *xh, *h1h, *h2h, *h3h, *Gh, *Bh, *winh, *wI, *wshh, *whh, *w2h;
    float *Ac, *Bc, *Gb;
    cudaGetSymbolAddress((void**)&xh,  g_xh);
    cudaGetSymbolAddress((void**)&h1h, g_h1h);
    cudaGetSymbolAddress((void**)&h2h, g_h2h);
    cudaGetSymbolAddress((void**)&h3h, g_h3h);
    cudaGetSymbolAddress((void**)&Gh,  g_Gh);
    cudaGetSymbolAddress((void**)&Bh,  g_Bh);
    cudaGetSymbolAddress((void**)&winh, g_winh);
    cudaGetSymbolAddress((void**)&wI,   g_wI);
    cudaGetSymbolAddress((void**)&wshh, g_wshh);
    cudaGetSymbolAddress((void**)&whh,  g_whh);
    cudaGetSymbolAddress((void**)&w2h,  g_w2h);
    cudaGetSymbolAddress((void**)&Ac, g_Ac);
    cudaGetSymbolAddress((void**)&Bc, g_Bc);
    cudaGetSymbolAddress((void**)&Gb, g_Gb);

    // half-pipeline grids (rows HSEQ each)
    const dim3 gHypH (HYP / BN,   HSEQ / BM);   //  8 x 32
    const dim3 gPairH(2*HYP / BN, HSEQ / BM);   // 16 x 32
    const dim3 gHidH (HIDN / BN,  HSEQ / BM);   // 32 x 32

    // ---- fork ----
    cudaEventRecord(evRoot, 0);
    cudaStreamWaitEvent(s2, evRoot, 0);

    // stream 0: x + w_in conversion;  stream s2: weight conversion
    cvtA<<<(A1/4 + 255)/256, 256>>>(x, w_in, xh, winh);
    cudaEventRecord(evX, 0);
    cvtB<<<(B3/4 + 255)/256, 256, 0, s2>>>(wg0, wg0g, wg_sh, w_h, w2,
                                           wI, wshh, whh, w2h);
    cudaEventRecord(evW, s2);

    // cross-deps: each chain needs both conversions
    cudaStreamWaitEvent(0, evW, 0);    // chain A (rows 0..HSEQ-1) on stream 0
    cudaStreamWaitEvent(s2, evX, 0);   // chain B (rows HSEQ..SEQ-1) on s2

    // pointer offsets for half 1
    const size_t oX  = (size_t)HSEQ * INP;
    const size_t oHy = (size_t)HSEQ * HYP;
    const size_t oHd = (size_t)HSEQ * HIDN;

    // ---- chain A (stream 0, rows 0..4095) ----
    gemm_f16<<<gHypH, NTHREADS, SMEM_DYN>>>(xh, winh, b_in, nullptr, nullptr,
                                            HYP, INP, HYP, M_PLAIN, h1h);
    gemm_f16<<<gHidH, NTHREADS, SMEM_DYN>>>(xh, w2h, b2, nullptr, nullptr,
                                            HIDN, INP, HIDN, M_PLAIN, Gh);
    gemm_f16<<<gPairH, NTHREADS, SMEM_DYN>>>(h1h, wI, bg0, bg0g, nullptr,
                                             2*HYP, HYP, HYP, M_PAIR, h2h);
    gemm_f16<<<gHypH, NTHREADS, SMEM_DYN>>>(h2h, wshh, bg_sh, nullptr, nullptr,
                                            HYP, HYP, HYP, M_SILU, h3h);
    gemm_f16<<<gHidH, NTHREADS, SMEM_DYN>>>(h3h, whh, b_h, nullptr, Gh,
                                            HIDN, HYP, HIDN, M_GATE, Bh);
    scan_pass1<<<(NCHUNK/2)*HIDN/256, 256>>>(Bh, Ac, Bc, 0);

    // ---- chain B (stream s2, rows 4096..8191) ----
    gemm_f16<<<gHypH, NTHREADS, SMEM_DYN, s2>>>(xh + oX, winh, b_in, nullptr, nullptr,
                                                HYP, INP, HYP, M_PLAIN, h1h + oHy);
    gemm_f16<<<gHidH, NTHREADS, SMEM_DYN, s2>>>(xh + oX, w2h, b2, nullptr, nullptr,
                                                HIDN, INP, HIDN, M_PLAIN, Gh + oHd);
    gemm_f16<<<gPairH, NTHREADS, SMEM_DYN, s2>>>(h1h + oHy, wI, bg0, bg0g, nullptr,
                                                 2*HYP, HYP, HYP, M_PAIR, h2h + oHy);
    gemm_f16<<<gHypH, NTHREADS, SMEM_DYN, s2>>>(h2h + oHy, wshh, bg_sh, nullptr, nullptr,
                                                HYP, HYP, HYP, M_SILU, h3h + oHy);
    gemm_f16<<<gHidH, NTHREADS, SMEM_DYN, s2>>>(h3h + oHy, whh, b_h, nullptr, Gh + oHd,
                                                HIDN, HYP, HIDN, M_GATE, Bh + oHd);
    scan_pass1<<<(NCHUNK/2)*HIDN/256, 256, 0, s2>>>(Bh, Ac, Bc, NCHUNK/2);
    cudaEventRecord(evHalf, s2);

    // ---- join: combine + pass2 on stream 0 ----
    cudaStreamWaitEvent(0, evHalf, 0);
    scan_combine<<<HIDN/256, 256>>>(hidden, Ac, Bc, Gb);
    scan_pass2<<<NCHUNK*HIDN/256, 256>>>(Bh, Gb, out, hlast, write_h);
}

// round 14
// speedup vs baseline: 1.1584x; 1.0127x over previous
#include <cuda_runtime.h>
#include <cuda_fp16.h>
#include <stdint.h>
#include <math.h>

#define SEQ   8192
#define INP   512
#define HYP   1024
#define HIDN  4096
#define CHUNK 128
#define NCHUNK (SEQ/CHUNK)   // 64
#define HSEQ  (SEQ/2)        // 4096 rows per half-pipeline

// ---------------- scratch (static __device__, no allocations) ----------------
__device__ __half g_xh  [SEQ*INP];
__device__ __half g_h1h [SEQ*HYP];
__device__ __half g_h2h [SEQ*HYP];
__device__ __half g_h3h [SEQ*HYP];
__device__ __half g_Gh  [SEQ*HIDN];
__device__ __half g_Bh  [SEQ*HIDN];
__device__ __half g_winh[HYP*INP];
__device__ __half g_wI  [2*HYP*HYP];         // interleaved wg0/wg0g
__device__ __half g_wshh[HYP*HYP];
__device__ __half g_whh [HIDN*HYP];
__device__ __half g_w2h [HIDN*INP];
__device__ float g_Ac[NCHUNK*HIDN];
__device__ float g_Bc[NCHUNK*HIDN];
__device__ float g_Gb[(NCHUNK+1)*HIDN];

// ---------------- PTX helpers (sm_100-portable only) --------------------------
__device__ __forceinline__ uint32_t smem_u32(const void* p) {
    uint32_t a;
    asm("{ .reg .u64 t; cvta.to.shared.u64 t, %1; cvt.u32.u64 %0, t; }" : "=r"(a) : "l"(p));
    return a;
}
__device__ __forceinline__ void cp16(uint32_t dst, const void* src) {
    asm volatile("cp.async.cg.shared.global [%0], [%1], 16;" :: "r"(dst), "l"(src));
}
__device__ __forceinline__ void cp_commit() { asm volatile("cp.async.commit_group;"); }
template <int N> __device__ __forceinline__ void cp_wait() {
    asm volatile("cp.async.wait_group %0;" :: "n"(N));
}
__device__ __forceinline__ void ldm4(uint32_t* r, uint32_t addr) {
    asm volatile("ldmatrix.sync.aligned.m8n8.x4.shared.b16 {%0,%1,%2,%3}, [%4];"
                 : "=r"(r[0]), "=r"(r[1]), "=r"(r[2]), "=r"(r[3]) : "r"(addr));
}
__device__ __forceinline__ void mma16816(float* d, const uint32_t* a, const uint32_t* b) {
    asm volatile(
        "mma.sync.aligned.m16n8k16.row.col.f32.f16.f16.f32 "
        "{%0,%1,%2,%3}, {%4,%5,%6,%7}, {%8,%9}, {%0,%1,%2,%3};"
        : "+f"(d[0]), "+f"(d[1]), "+f"(d[2]), "+f"(d[3])
        : "r"(a[0]), "r"(a[1]), "r"(a[2]), "r"(a[3]), "r"(b[0]), "r"(b[1]));
}

// ---------------- fp16 GEMM (R8 config): 256 thr, 2x4 warps, 64x32 tiles ------
#define BM 128
#define BN 128
#define BKE 64
#define OPER 16384
#define STAGE (2*OPER)           // 32 KB
#define NSTAGE 3
#define SMEM_DYN (NSTAGE*STAGE)  // 98304 B
#define NTHREADS 256

#define M_PLAIN 0
#define M_GATE  1
#define M_SILU  2
#define M_PAIR  3   // interleaved value/gate cols -> v*sigm(g); bias/bias2 = bg0/bg0g

__device__ __forceinline__ float sigm(float x) { return 1.f / (1.f + expf(-x)); }

__global__ __launch_bounds__(NTHREADS, 2)
void gemm_f16(const __half* __restrict__ A, const __half* __restrict__ W,
              const float* __restrict__ bias, const float* __restrict__ bias2,
              const __half* __restrict__ aux,
              int N, int K, int Nout, int mode, __half* __restrict__ Ch)
{
    extern __shared__ char dsmem[];
    const int tid = threadIdx.x, lane = tid & 31, wid = tid >> 5;
    const int warp_m = wid >> 2, warp_n = wid & 3;          // 2 x 4 warp grid
    const int bm = blockIdx.y * BM, bn = blockIdx.x * BN;
    const uint32_t sbase = smem_u32(dsmem);

    float acc[4][4][4];
#pragma unroll
    for (int i = 0; i < 4; i++)
#pragma unroll
        for (int j = 0; j < 4; j++)
#pragma unroll
            for (int q = 0; q < 4; q++) acc[i][j][q] = 0.f;

    uint32_t aadr[4], badr[2];
    {
        const uint32_t ksA = (lane >> 4) & 1;
        int rA = (lane & 7) + ((lane >> 3) & 1) * 8;
#pragma unroll
        for (int mf = 0; mf < 4; mf++) {
            int r = warp_m * 64 + mf * 16 + rA;
            aadr[mf] = (uint32_t)(r * 128) + ((ksA ^ (uint32_t)(r & 7)) << 4);
        }
        const uint32_t ksB = (lane >> 3) & 1;
        int rB = (lane & 7) + ((lane >> 4) & 1) * 8;
#pragma unroll
        for (int g = 0; g < 2; g++) {
            int r = warp_n * 32 + g * 16 + rB;
            badr[g] = (uint32_t)(r * 128) + ((ksB ^ (uint32_t)(r & 7)) << 4);
        }
    }

    const int spt = K / BKE;

    auto load_stage = [&](int k0, int buf) {
        uint32_t dA = sbase + (uint32_t)buf * STAGE;
        uint32_t dB = dA + OPER;
#pragma unroll
        for (int i = 0; i < 4; i++) {
            int c = i * NTHREADS + tid;
            int r = c >> 3, seg = c & 7;
            uint32_t o = (uint32_t)(r * 128 + ((seg ^ (r & 7)) << 4));
            cp16(dA + o, A + (size_t)(bm + r) * K + k0 + seg * 8);
            cp16(dB + o, W + (size_t)(bn + r) * K + k0 + seg * 8);
        }
    };

    load_stage(0, 0);  cp_commit();
    load_stage(BKE, 1); cp_commit();

    for (int s = 0; s < spt; s++) {
        const int buf = s % NSTAGE;
        if (s < spt - 1) cp_wait<1>(); else cp_wait<0>();
        __syncthreads();
        if (s + 2 < spt) { load_stage((s + 2) * BKE, (s + 2) % NSTAGE); cp_commit(); }

        const uint32_t sA = sbase + (uint32_t)buf * STAGE;
        const uint32_t sB = sA + OPER;
#pragma unroll
        for (int ks = 0; ks < 4; ks++) {
            const uint32_t kx = (uint32_t)(ks << 5);
            uint32_t br[8];
            ldm4(br,     sB + (badr[0] ^ kx));
            ldm4(br + 4, sB + (badr[1] ^ kx));
#pragma unroll
            for (int mf = 0; mf < 4; mf++) {
                uint32_t ar[4];
                ldm4(ar, sA + (aadr[mf] ^ kx));
#pragma unroll
                for (int nf = 0; nf < 4; nf++)
                    mma16816(acc[mf][nf], ar, br + nf * 2);
            }
        }
    }

    // ------------- fused epilogue -------------
    float2 bv[4];
#pragma unroll
    for (int nf = 0; nf < 4; nf++) {
        int nloc = bn + warp_n * 32 + nf * 8 + (lane & 3) * 2;
        if (mode == M_PAIR) {
            bv[nf].x = bias[nloc >> 1];
            bv[nf].y = bias2[nloc >> 1];
        } else {
            bv[nf] = *(const float2*)&bias[nloc];
        }
    }

#pragma unroll
    for (int mf = 0; mf < 4; mf++) {
#pragma unroll
        for (int h = 0; h < 2; h++) {
            const int row = bm + warp_m * 64 + mf * 16 + (lane >> 2) + h * 8;
#pragma unroll
            for (int nf = 0; nf < 4; nf++) {
                const int nloc = bn + warp_n * 32 + nf * 8 + (lane & 3) * 2;
                float v0 = acc[mf][nf][h * 2 + 0] + bv[nf].x;
                float v1 = acc[mf][nf][h * 2 + 1] + bv[nf].y;
                if (mode == M_PAIR) {
                    Ch[(size_t)row * Nout + (nloc >> 1)] = __float2half(v0 * sigm(v1));
                } else {
                    if (mode == M_GATE) {
                        __half2 g = *(const __half2*)&aux[(size_t)row * N + nloc];
                        v0 *= sigm(__half2float(g.x));
                        v1 *= sigm(__half2float(g.y));
                    } else if (mode == M_SILU) {
                        v0 *= sigm(v0); v1 *= sigm(v1);
                    }
                    __half2 o; o.x = __float2half(v0); o.y = __float2half(v1);
                    *(__half2*)&Ch[(size_t)row * Nout + nloc] = o;
                }
            }
        }
    }
}

// ---------------- conversion kernels (split for overlap) -----------------------
__device__ __forceinline__ void cvt4(const float* s, __half* d) {
    float4 v = *(const float4*)s;
    __half2 a; a.x = __float2half(v.x); a.y = __float2half(v.y);
    __half2 b; b.x = __float2half(v.z); b.y = __float2half(v.w);
    *(__half2*)d       = a;
    *(__half2*)(d + 2) = b;
}

#define A0 (SEQ*INP)
#define A1 (A0 + HYP*INP)
__global__ void cvtA(const float* __restrict__ x, const float* __restrict__ w_in,
                     __half* __restrict__ xh, __half* __restrict__ winh)
{
    int i = (blockIdx.x * blockDim.x + threadIdx.x) * 4;
    if (i < A0)      cvt4(x + i, xh + i);
    else if (i < A1) { int j = i - A0; cvt4(w_in + j, winh + j); }
}

#define B0 (2*HYP*HYP)
#define B1 (B0 + HYP*HYP)
#define B2 (B1 + HIDN*HYP)
#define B3 (B2 + HIDN*INP)
__global__ void cvtB(const float* __restrict__ wg0, const float* __restrict__ wg0g,
                     const float* __restrict__ wg_sh, const float* __restrict__ w_h,
                     const float* __restrict__ w2,
                     __half* __restrict__ wI, __half* __restrict__ wshh,
                     __half* __restrict__ whh, __half* __restrict__ w2h)
{
    int i = (blockIdx.x * blockDim.x + threadIdx.x) * 4;
    if (i < B0) {
        int r = i >> 10, k = i & (HYP - 1);
        const float* s = (r & 1) ? wg0g : wg0;
        cvt4(s + ((size_t)(r >> 1) << 10) + k, wI + i);
    } else if (i < B1) { int j = i - B0; cvt4(wg_sh + j, wshh + j); }
    else if (i < B2)   { int j = i - B1; cvt4(w_h + j, whh + j); }
    else if (i < B3)   { int j = i - B2; cvt4(w2 + j, w2h + j); }
}

// ---------------- rotated-frame relu scan (fp16 B, half-split pass1) ----------
__global__ void scan_pass1(const __half* __restrict__ B,
                           float* __restrict__ Ac, float* __restrict__ Bc,
                           int chunk_base)
{
    int t     = blockIdx.x * blockDim.x + threadIdx.x;
    int lane  = t & (HIDN - 1);
    int chnk  = chunk_base + (t >> 12);
    float Aa = -1e30f, Ss = 0.f;
    int base = chnk * CHUNK;
#pragma unroll 8
    for (int i = 0; i < CHUNK; i++) {
        int row = base + i;
        float b = __half2float(B[(size_t)row * HIDN + ((lane + row) & (HIDN - 1))]);
        Aa = fmaxf(0.f, b + Aa);
        Ss += b;
    }
    Ac[chnk * HIDN + lane] = Aa;
    Bc[chnk * HIDN + lane] = Ss;
}

// batched loads (MLP=16) -> same per-lane arithmetic order, far less latency
__global__ void scan_combine(const float* __restrict__ hidden,
                             const float* __restrict__ Ac, const float* __restrict__ Bc,
                             float* __restrict__ Gb)
{
    int lane = blockIdx.x * blockDim.x + threadIdx.x;
    float gv = hidden[(lane - 1) & (HIDN - 1)];
    Gb[lane] = gv;
    for (int c0 = 0; c0 < NCHUNK; c0 += 8) {
        float a[8], b[8];
#pragma unroll
        for (int j = 0; j < 8; j++) {
            a[j] = Ac[(c0 + j) * HIDN + lane];
            b[j] = Bc[(c0 + j) * HIDN + lane];
        }
#pragma unroll
        for (int j = 0; j < 8; j++) {
            gv = fmaxf(a[j], b[j] + gv);
            Gb[(c0 + j + 1) * HIDN + lane] = gv;
        }
    }
}

__global__ void scan_pass2(const __half* __restrict__ B, const float* __restrict__ Gb,
                           float* __restrict__ out, float* __restrict__ hlast, int write_h)
{
    int t    = blockIdx.x * blockDim.x + threadIdx.x;
    int lane = t & (HIDN - 1);
    int chnk = t >> 12;
    float gv = Gb[chnk * HIDN + lane];
    int base = chnk * CHUNK;
#pragma unroll 4
    for (int i = 0; i < CHUNK; i++) {
        int row = base + i;
        int col = (lane + row) & (HIDN - 1);
        gv = fmaxf(0.f, __half2float(B[(size_t)row * HIDN + col]) + gv);
        out[(size_t)row * HIDN + col] = gv;
    }
    if (write_h && chnk == NCHUNK - 1)
        hlast[(lane - 1) & (HIDN - 1)] = gv;
}

// ---------------- launch ------------------------------------------------------
extern "C" void kernel_launch(void* const* d_in, const int* in_sizes, int n_in,
                              void* d_out, int out_size)
{
    const float* x      = (const float*)d_in[0];
    const float* hidden = (const float*)d_in[1];
    const float* w_in   = (const float*)d_in[2];
    const float* b_in   = (const float*)d_in[3];
    const float* wg0    = (const float*)d_in[4];
    const float* bg0    = (const float*)d_in[5];
    const float* wg0g   = (const float*)d_in[6];
    const float* bg0g   = (const float*)d_in[7];
    const float* wg_sh  = (const float*)d_in[8];
    const float* bg_sh  = (const float*)d_in[9];
    const float* w_h    = (const float*)d_in[10];
    const float* b_h    = (const float*)d_in[11];
    const float* w2     = (const float*)d_in[12];
    const float* b2     = (const float*)d_in[13];

    float* out   = (float*)d_out;
    float* hlast = out + (size_t)SEQ * HIDN;
    int write_h  = (out_size >= SEQ * HIDN + HIDN) ? 1 : 0;

    cudaFuncSetAttribute(gemm_f16, cudaFuncAttributeMaxDynamicSharedMemorySize, SMEM_DYN);

    // Streams + events: created once on the first (correctness) call.
    static cudaStream_t s2 = nullptr, s3 = nullptr;
    static cudaEvent_t evRoot = nullptr, evX = nullptr, evW = nullptr, evHalf = nullptr;
    if (s2 == nullptr) {
        cudaStreamCreateWithFlags(&s2, cudaStreamNonBlocking);
        cudaStreamCreateWithFlags(&s3, cudaStreamNonBlocking);
        cudaEventCreateWithFlags(&evRoot, cudaEventDisableTiming);
        cudaEventCreateWithFlags(&evX,    cudaEventDisableTiming);
        cudaEventCreateWithFlags(&evW,    cudaEventDisableTiming);
        cudaEventCreateWithFlags(&evHalf, cudaEventDisableTiming);
    }

    __half *xh, *h1h, *h2h, *h3h, *Gh, *Bh, *winh, *wI, *wshh, *whh, *w2h;
    float *Ac, *Bc, *Gb;
    cudaGetSymbolAddress((void**)&xh,  g_xh);
    cudaGetSymbolAddress((void**)&h1h, g_h1h);
    cudaGetSymbolAddress((void**)&h2h, g_h2h);
    cudaGetSymbolAddress((void**)&h3h, g_h3h);
    cudaGetSymbolAddress((void**)&Gh,  g_Gh);
    cudaGetSymbolAddress((void**)&Bh,  g_Bh);
    cudaGetSymbolAddress((void**)&winh, g_winh);
    cudaGetSymbolAddress((void**)&wI,   g_wI);
    cudaGetSymbolAddress((void**)&wshh, g_wshh);
    cudaGetSymbolAddress((void**)&whh,  g_whh);
    cudaGetSymbolAddress((void**)&w2h,  g_w2h);
    cudaGetSymbolAddress((void**)&Ac, g_Ac);
    cudaGetSymbolAddress((void**)&Bc, g_Bc);
    cudaGetSymbolAddress((void**)&Gb, g_Gb);

    const dim3 gHypH (HYP / BN,   HSEQ / BM);   //  8 x 32
    const dim3 gPairH(2*HYP / BN, HSEQ / BM);   // 16 x 32
    const dim3 gHidH (HIDN / BN,  HSEQ / BM);   // 32 x 32

    // ---- fork ----
    cudaEventRecord(evRoot, 0);
    cudaStreamWaitEvent(s2, evRoot, 0);
    cudaStreamWaitEvent(s3, evRoot, 0);

    // stream 0: x + w_in conversion (small); stream s3: big weight conversion
    cvtA<<<(A1/4 + 255)/256, 256>>>(x, w_in, xh, winh);
    cudaEventRecord(evX, 0);
    cvtB<<<(B3/4 + 255)/256, 256, 0, s3>>>(wg0, wg0g, wg_sh, w_h, w2,
                                           wI, wshh, whh, w2h);
    cudaEventRecord(evW, s3);

    const size_t oX  = (size_t)HSEQ * INP;
    const size_t oHy = (size_t)HSEQ * HYP;
    const size_t oHd = (size_t)HSEQ * HIDN;

    // ---- chain A (stream 0, rows 0..4095): h1 needs only cvtA ----
    gemm_f16<<<gHypH, NTHREADS, SMEM_DYN>>>(xh, winh, b_in, nullptr, nullptr,
                                            HYP, INP, HYP, M_PLAIN, h1h);
    cudaStreamWaitEvent(0, evW, 0);    // G/pair/h3/B need cvtB weights
    gemm_f16<<<gHidH, NTHREADS, SMEM_DYN>>>(xh, w2h, b2, nullptr, nullptr,
                                            HIDN, INP, HIDN, M_PLAIN, Gh);
    gemm_f16<<<gPairH, NTHREADS, SMEM_DYN>>>(h1h, wI, bg0, bg0g, nullptr,
                                             2*HYP, HYP, HYP, M_PAIR, h2h);
    gemm_f16<<<gHypH, NTHREADS, SMEM_DYN>>>(h2h, wshh, bg_sh, nullptr, nullptr,
                                            HYP, HYP, HYP, M_SILU, h3h);
    gemm_f16<<<gHidH, NTHREADS, SMEM_DYN>>>(h3h, whh, b_h, nullptr, Gh,
                                            HIDN, HYP, HIDN, M_GATE, Bh);
    scan_pass1<<<(NCHUNK/2)*HIDN/256, 256>>>(Bh, Ac, Bc, 0);

    // ---- chain B (stream s2, rows 4096..8191) ----
    cudaStreamWaitEvent(s2, evX, 0);   // h1B needs cvtA only
    gemm_f16<<<gHypH, NTHREADS, SMEM_DYN, s2>>>(xh + oX, winh, b_in, nullptr, nullptr,
                                                HYP, INP, HYP, M_PLAIN, h1h + oHy);
    cudaStreamWaitEvent(s2, evW, 0);
    gemm_f16<<<gHidH, NTHREADS, SMEM_DYN, s2>>>(xh + oX, w2h, b2, nullptr, nullptr,
                                                HIDN, INP, HIDN, M_PLAIN, Gh + oHd);
    gemm_f16<<<gPairH, NTHREADS, SMEM_DYN, s2>>>(h1h + oHy, wI, bg0, bg0g, nullptr,
                                                 2*HYP, HYP, HYP, M_PAIR, h2h + oHy);
    gemm_f16<<<gHypH, NTHREADS, SMEM_DYN, s2>>>(h2h + oHy, wshh, bg_sh, nullptr, nullptr,
                                                HYP, HYP, HYP, M_SILU, h3h + oHy);
    gemm_f16<<<gHidH, NTHREADS, SMEM_DYN, s2>>>(h3h + oHy, whh, b_h, nullptr, Gh + oHd,
                                                HIDN, HYP, HIDN, M_GATE, Bh + oHd);
    scan_pass1<<<(NCHUNK/2)*HIDN/256, 256, 0, s2>>>(Bh, Ac, Bc, NCHUNK/2);
    cudaEventRecord(evHalf, s2);

    // ---- join: combine + pass2 on stream 0 ----
    cudaStreamWaitEvent(0, evHalf, 0);
    scan_combine<<<HIDN/256, 256>>>(hidden, Ac, Bc, Gb);
    scan_pass2<<<NCHUNK*HIDN/256, 256>>>(Bh, Gb, out, hlast, write_h);
}

// round 15
// speedup vs baseline: 1.1731x; 1.0127x over previous
#include <cuda_runtime.h>
#include <cuda_fp16.h>
#include <stdint.h>
#include <math.h>

#define SEQ   8192
#define INP   512
#define HYP   1024
#define HIDN  4096
#define CHUNK 128
#define NCHUNK (SEQ/CHUNK)   // 64
#define HSEQ  (SEQ/2)        // 4096 rows per half-pipeline

// ---------------- scratch (static __device__, no allocations) ----------------
__device__ __half g_xh  [SEQ*INP];
__device__ __half g_h1h [SEQ*HYP];
__device__ __half g_h2h [SEQ*HYP];
__device__ __half g_h3h [SEQ*HYP];
__device__ __half g_Bh  [SEQ*HIDN];
__device__ __half g_winh[HYP*INP];
__device__ __half g_wI  [2*HYP*HYP];         // interleaved wg0/wg0g
__device__ __half g_wshh[HYP*HYP];
__device__ __half g_whh [HIDN*HYP];
__device__ __half g_w2h [HIDN*INP];
__device__ float g_Ac[NCHUNK*HIDN];
__device__ float g_Bc[NCHUNK*HIDN];
__device__ float g_Gb[(NCHUNK+1)*HIDN];

// ---------------- PTX helpers (sm_100-portable only) --------------------------
__device__ __forceinline__ uint32_t smem_u32(const void* p) {
    uint32_t a;
    asm("{ .reg .u64 t; cvta.to.shared.u64 t, %1; cvt.u32.u64 %0, t; }" : "=r"(a) : "l"(p));
    return a;
}
__device__ __forceinline__ void cp16(uint32_t dst, const void* src) {
    asm volatile("cp.async.cg.shared.global [%0], [%1], 16;" :: "r"(dst), "l"(src));
}
__device__ __forceinline__ void cp_commit() { asm volatile("cp.async.commit_group;"); }
template <int N> __device__ __forceinline__ void cp_wait() {
    asm volatile("cp.async.wait_group %0;" :: "n"(N));
}
__device__ __forceinline__ void ldm4(uint32_t* r, uint32_t addr) {
    asm volatile("ldmatrix.sync.aligned.m8n8.x4.shared.b16 {%0,%1,%2,%3}, [%4];"
                 : "=r"(r[0]), "=r"(r[1]), "=r"(r[2]), "=r"(r[3]) : "r"(addr));
}
__device__ __forceinline__ void mma16816(float* d, const uint32_t* a, const uint32_t* b) {
    asm volatile(
        "mma.sync.aligned.m16n8k16.row.col.f32.f16.f16.f32 "
        "{%0,%1,%2,%3}, {%4,%5,%6,%7}, {%8,%9}, {%0,%1,%2,%3};"
        : "+f"(d[0]), "+f"(d[1]), "+f"(d[2]), "+f"(d[3])
        : "r"(a[0]), "r"(a[1]), "r"(a[2]), "r"(a[3]), "r"(b[0]), "r"(b[1]));
}

// ---------------- common GEMM config ------------------------------------------
#define BM 128
#define BN 128
#define BKE 64
#define OPER 16384
#define STAGE (2*OPER)           // 32 KB
#define NSTAGE 3
#define SMEM_DYN (NSTAGE*STAGE)  // 98304 B
#define NTHREADS 256

#define M_PLAIN 0
#define M_GATE  1
#define M_SILU  2
#define M_PAIR  3

__device__ __forceinline__ float sigm(float x) { return 1.f / (1.f + expf(-x)); }

// address setup shared by both kernels
#define GEMM_ADDR_SETUP()                                                       \
    uint32_t aadr[4], badr[2];                                                  \
    {                                                                           \
        const uint32_t ksA = (lane >> 4) & 1;                                   \
        int rA = (lane & 7) + ((lane >> 3) & 1) * 8;                            \
        _Pragma("unroll")                                                       \
        for (int mf = 0; mf < 4; mf++) {                                        \
            int r = warp_m * 64 + mf * 16 + rA;                                 \
            aadr[mf] = (uint32_t)(r * 128) + ((ksA ^ (uint32_t)(r & 7)) << 4);  \
        }                                                                       \
        const uint32_t ksB = (lane >> 3) & 1;                                   \
        int rB = (lane & 7) + ((lane >> 4) & 1) * 8;                            \
        _Pragma("unroll")                                                       \
        for (int g = 0; g < 2; g++) {                                           \
            int r = warp_n * 32 + g * 16 + rB;                                  \
            badr[g] = (uint32_t)(r * 128) + ((ksB ^ (uint32_t)(r & 7)) << 4);   \
        }                                                                       \
    }

// pipelined K-loop over (Aptr, Wptr) with K elems, accumulating into acc
#define GEMM_MAIN_LOOP(Aptr, Wptr, Kelems)                                      \
    {                                                                           \
        const int spt = (Kelems) / BKE;                                         \
        auto load_stage = [&](int k0, int buf) {                                \
            uint32_t dA = sbase + (uint32_t)buf * STAGE;                        \
            uint32_t dB = dA + OPER;                                            \
            _Pragma("unroll")                                                   \
            for (int i = 0; i < 4; i++) {                                       \
                int c = i * NTHREADS + tid;                                     \
                int r = c >> 3, seg = c & 7;                                    \
                uint32_t o = (uint32_t)(r * 128 + ((seg ^ (r & 7)) << 4));      \
                cp16(dA + o, (Aptr) + (size_t)(bm + r) * (Kelems) + k0 + seg * 8); \
                cp16(dB + o, (Wptr) + (size_t)(bn + r) * (Kelems) + k0 + seg * 8); \
            }                                                                   \
        };                                                                      \
        load_stage(0, 0);  cp_commit();                                         \
        load_stage(BKE, 1); cp_commit();                                        \
        for (int s = 0; s < spt; s++) {                                         \
            const int buf = s % NSTAGE;                                         \
            if (s < spt - 1) cp_wait<1>(); else cp_wait<0>();                   \
            __syncthreads();                                                    \
            if (s + 2 < spt) { load_stage((s + 2) * BKE, (s + 2) % NSTAGE); cp_commit(); } \
            const uint32_t sA = sbase + (uint32_t)buf * STAGE;                  \
            const uint32_t sB = sA + OPER;                                      \
            _Pragma("unroll")                                                   \
            for (int ks = 0; ks < 4; ks++) {                                    \
                const uint32_t kx = (uint32_t)(ks << 5);                        \
                uint32_t br[8];                                                 \
                ldm4(br,     sB + (badr[0] ^ kx));                              \
                ldm4(br + 4, sB + (badr[1] ^ kx));                              \
                _Pragma("unroll")                                               \
                for (int mf = 0; mf < 4; mf++) {                                \
                    uint32_t ar[4];                                             \
                    ldm4(ar, sA + (aadr[mf] ^ kx));                             \
                    _Pragma("unroll")                                           \
                    for (int nf = 0; nf < 4; nf++)                              \
                        mma16816(acc[mf][nf], ar, br + nf * 2);                 \
                }                                                               \
            }                                                                   \
        }                                                                       \
    }

// ---------------- generic fp16 GEMM (h1 / pair / h3) ---------------------------
__global__ __launch_bounds__(NTHREADS, 2)
void gemm_f16(const __half* __restrict__ A, const __half* __restrict__ W,
              const float* __restrict__ bias, const float* __restrict__ bias2,
              const __half* __restrict__ aux,
              int N, int K, int Nout, int mode, __half* __restrict__ Ch)
{
    extern __shared__ char dsmem[];
    const int tid = threadIdx.x, lane = tid & 31, wid = tid >> 5;
    const int warp_m = wid >> 2, warp_n = wid & 3;
    const int bm = blockIdx.y * BM, bn = blockIdx.x * BN;
    const uint32_t sbase = smem_u32(dsmem);

    float acc[4][4][4];
#pragma unroll
    for (int i = 0; i < 4; i++)
#pragma unroll
        for (int j = 0; j < 4; j++)
#pragma unroll
            for (int q = 0; q < 4; q++) acc[i][j][q] = 0.f;

    GEMM_ADDR_SETUP();
    GEMM_MAIN_LOOP(A, W, K);

    float2 bv[4];
#pragma unroll
    for (int nf = 0; nf < 4; nf++) {
        int nloc = bn + warp_n * 32 + nf * 8 + (lane & 3) * 2;
        if (mode == M_PAIR) {
            bv[nf].x = bias[nloc >> 1];
            bv[nf].y = bias2[nloc >> 1];
        } else {
            bv[nf] = *(const float2*)&bias[nloc];
        }
    }

#pragma unroll
    for (int mf = 0; mf < 4; mf++) {
#pragma unroll
        for (int h = 0; h < 2; h++) {
            const int row = bm + warp_m * 64 + mf * 16 + (lane >> 2) + h * 8;
#pragma unroll
            for (int nf = 0; nf < 4; nf++) {
                const int nloc = bn + warp_n * 32 + nf * 8 + (lane & 3) * 2;
                float v0 = acc[mf][nf][h * 2 + 0] + bv[nf].x;
                float v1 = acc[mf][nf][h * 2 + 1] + bv[nf].y;
                if (mode == M_PAIR) {
                    Ch[(size_t)row * Nout + (nloc >> 1)] = __float2half(v0 * sigm(v1));
                } else {
                    if (mode == M_GATE) {
                        __half2 g = *(const __half2*)&aux[(size_t)row * N + nloc];
                        v0 *= sigm(__half2float(g.x));
                        v1 *= sigm(__half2float(g.y));
                    } else if (mode == M_SILU) {
                        v0 *= sigm(v0); v1 *= sigm(v1);
                    }
                    __half2 o; o.x = __float2half(v0); o.y = __float2half(v1);
                    *(__half2*)&Ch[(size_t)row * Nout + nloc] = o;
                }
            }
        }
    }
}

// ---------------- fused gate+value GEMM: Bh = (h3@whh^T+b_h)*sigm(x@w2^T+b2) ---
__global__ __launch_bounds__(NTHREADS, 2)
void gemm_fused_gb(const __half* __restrict__ Ax, const __half* __restrict__ W2,
                   const __half* __restrict__ Ah, const __half* __restrict__ Wh,
                   const float* __restrict__ bias_g, const float* __restrict__ bias_v,
                   __half* __restrict__ Bh)
{
    extern __shared__ char dsmem[];
    const int tid = threadIdx.x, lane = tid & 31, wid = tid >> 5;
    const int warp_m = wid >> 2, warp_n = wid & 3;
    const int bm = blockIdx.y * BM, bn = blockIdx.x * BN;
    const uint32_t sbase = smem_u32(dsmem);

    float acc[4][4][4];
#pragma unroll
    for (int i = 0; i < 4; i++)
#pragma unroll
        for (int j = 0; j < 4; j++)
#pragma unroll
            for (int q = 0; q < 4; q++) acc[i][j][q] = 0.f;

    GEMM_ADDR_SETUP();

    // ---- phase 1: gate = x @ w2^T  (K = INP) ----
    GEMM_MAIN_LOOP(Ax, W2, INP);
    __syncthreads();   // all warps done reading phase-1 smem before reuse

    // pack gate (+bias) to fp16 pairs — identical rounding to the old Gh store
    uint32_t gate[4][4][2];
    {
        float2 bg[4];
#pragma unroll
        for (int nf = 0; nf < 4; nf++)
            bg[nf] = *(const float2*)&bias_g[bn + warp_n * 32 + nf * 8 + (lane & 3) * 2];
#pragma unroll
        for (int mf = 0; mf < 4; mf++)
#pragma unroll
            for (int nf = 0; nf < 4; nf++)
#pragma unroll
                for (int h = 0; h < 2; h++) {
                    __half2 g;
                    g.x = __float2half(acc[mf][nf][h * 2 + 0] + bg[nf].x);
                    g.y = __float2half(acc[mf][nf][h * 2 + 1] + bg[nf].y);
                    gate[mf][nf][h] = *(uint32_t*)&g;
                    acc[mf][nf][h * 2 + 0] = 0.f;
                    acc[mf][nf][h * 2 + 1] = 0.f;
                }
    }

    // ---- phase 2: value = h3 @ whh^T  (K = HYP) ----
    GEMM_MAIN_LOOP(Ah, Wh, HYP);

    // ---- epilogue: Bh = (value + b_h) * sigm(gate) ----
    float2 bv[4];
#pragma unroll
    for (int nf = 0; nf < 4; nf++)
        bv[nf] = *(const float2*)&bias_v[bn + warp_n * 32 + nf * 8 + (lane & 3) * 2];

#pragma unroll
    for (int mf = 0; mf < 4; mf++) {
#pragma unroll
        for (int h = 0; h < 2; h++) {
            const int row = bm + warp_m * 64 + mf * 16 + (lane >> 2) + h * 8;
#pragma unroll
            for (int nf = 0; nf < 4; nf++) {
                const int nloc = bn + warp_n * 32 + nf * 8 + (lane & 3) * 2;
                __half2 g = *(__half2*)&gate[mf][nf][h];
                float v0 = (acc[mf][nf][h * 2 + 0] + bv[nf].x) * sigm(__half2float(g.x));
                float v1 = (acc[mf][nf][h * 2 + 1] + bv[nf].y) * sigm(__half2float(g.y));
                __half2 o; o.x = __float2half(v0); o.y = __float2half(v1);
                *(__half2*)&Bh[(size_t)row * HIDN + nloc] = o;
            }
        }
    }
}

// ---------------- conversion kernels ------------------------------------------
__device__ __forceinline__ void cvt4(const float* s, __half* d) {
    float4 v = *(const float4*)s;
    __half2 a; a.x = __float2half(v.x); a.y = __float2half(v.y);
    __half2 b; b.x = __float2half(v.z); b.y = __float2half(v.w);
    *(__half2*)d       = a;
    *(__half2*)(d + 2) = b;
}

#define A0 (SEQ*INP)
#define A1 (A0 + HYP*INP)
__global__ void cvtA(const float* __restrict__ x, const float* __restrict__ w_in,
                     __half* __restrict__ xh, __half* __restrict__ winh)
{
    int i = (blockIdx.x * blockDim.x + threadIdx.x) * 4;
    if (i < A0)      cvt4(x + i, xh + i);
    else if (i < A1) { int j = i - A0; cvt4(w_in + j, winh + j); }
}

#define B0 (2*HYP*HYP)
#define B1 (B0 + HYP*HYP)
#define B2 (B1 + HIDN*HYP)
#define B3 (B2 + HIDN*INP)
__global__ void cvtB(const float* __restrict__ wg0, const float* __restrict__ wg0g,
                     const float* __restrict__ wg_sh, const float* __restrict__ w_h,
                     const float* __restrict__ w2,
                     __half* __restrict__ wI, __half* __restrict__ wshh,
                     __half* __restrict__ whh, __half* __restrict__ w2h)
{
    int i = (blockIdx.x * blockDim.x + threadIdx.x) * 4;
    if (i < B0) {
        int r = i >> 10, k = i & (HYP - 1);
        const float* s = (r & 1) ? wg0g : wg0;
        cvt4(s + ((size_t)(r >> 1) << 10) + k, wI + i);
    } else if (i < B1) { int j = i - B0; cvt4(wg_sh + j, wshh + j); }
    else if (i < B2)   { int j = i - B1; cvt4(w_h + j, whh + j); }
    else if (i < B3)   { int j = i - B2; cvt4(w2 + j, w2h + j); }
}

// ---------------- rotated-frame relu scan -------------------------------------
__global__ void scan_pass1(const __half* __restrict__ B,
                           float* __restrict__ Ac, float* __restrict__ Bc,
                           int chunk_base)
{
    int t     = blockIdx.x * blockDim.x + threadIdx.x;
    int lane  = t & (HIDN - 1);
    int chnk  = chunk_base + (t >> 12);
    float Aa = -1e30f, Ss = 0.f;
    int base = chnk * CHUNK;
#pragma unroll 8
    for (int i = 0; i < CHUNK; i++) {
        int row = base + i;
        float b = __half2float(B[(size_t)row * HIDN + ((lane + row) & (HIDN - 1))]);
        Aa = fmaxf(0.f, b + Aa);
        Ss += b;
    }
    Ac[chnk * HIDN + lane] = Aa;
    Bc[chnk * HIDN + lane] = Ss;
}

__global__ void scan_combine(const float* __restrict__ hidden,
                             const float* __restrict__ Ac, const float* __restrict__ Bc,
                             float* __restrict__ Gb)
{
    int lane = blockIdx.x * blockDim.x + threadIdx.x;
    float gv = hidden[(lane - 1) & (HIDN - 1)];
    Gb[lane] = gv;
    for (int c0 = 0; c0 < NCHUNK; c0 += 8) {
        float a[8], b[8];
#pragma unroll
        for (int j = 0; j < 8; j++) {
            a[j] = Ac[(c0 + j) * HIDN + lane];
            b[j] = Bc[(c0 + j) * HIDN + lane];
        }
#pragma unroll
        for (int j = 0; j < 8; j++) {
            gv = fmaxf(a[j], b[j] + gv);
            Gb[(c0 + j + 1) * HIDN + lane] = gv;
        }
    }
}

__global__ void scan_pass2(const __half* __restrict__ B, const float* __restrict__ Gb,
                           float* __restrict__ out, float* __restrict__ hlast, int write_h)
{
    int t    = blockIdx.x * blockDim.x + threadIdx.x;
    int lane = t & (HIDN - 1);
    int chnk = t >> 12;
    float gv = Gb[chnk * HIDN + lane];
    int base = chnk * CHUNK;
#pragma unroll 4
    for (int i = 0; i < CHUNK; i++) {
        int row = base + i;
        int col = (lane + row) & (HIDN - 1);
        gv = fmaxf(0.f, __half2float(B[(size_t)row * HIDN + col]) + gv);
        out[(size_t)row * HIDN + col] = gv;
    }
    if (write_h && chnk == NCHUNK - 1)
        hlast[(lane - 1) & (HIDN - 1)] = gv;
}

// ---------------- launch ------------------------------------------------------
extern "C" void kernel_launch(void* const* d_in, const int* in_sizes, int n_in,
                              void* d_out, int out_size)
{
    const float* x      = (const float*)d_in[0];
    const float* hidden = (const float*)d_in[1];
    const float* w_in   = (const float*)d_in[2];
    const float* b_in   = (const float*)d_in[3];
    const float* wg0    = (const float*)d_in[4];
    const float* bg0    = (const float*)d_in[5];
    const float* wg0g   = (const float*)d_in[6];
    const float* bg0g   = (const float*)d_in[7];
    const float* wg_sh  = (const float*)d_in[8];
    const float* bg_sh  = (const float*)d_in[9];
    const float* w_h    = (const float*)d_in[10];
    const float* b_h    = (const float*)d_in[11];
    const float* w2     = (const float*)d_in[12];
    const float* b2     = (const float*)d_in[13];

    float* out   = (float*)d_out;
    float* hlast = out + (size_t)SEQ * HIDN;
    int write_h  = (out_size >= SEQ * HIDN + HIDN) ? 1 : 0;

    cudaFuncSetAttribute(gemm_f16, cudaFuncAttributeMaxDynamicSharedMemorySize, SMEM_DYN);
    cudaFuncSetAttribute(gemm_fused_gb, cudaFuncAttributeMaxDynamicSharedMemorySize, SMEM_DYN);

    static cudaStream_t s2 = nullptr, s3 = nullptr;
    static cudaEvent_t evRoot = nullptr, evX = nullptr, evW = nullptr, evHalf = nullptr;
    if (s2 == nullptr) {
        cudaStreamCreateWithFlags(&s2, cudaStreamNonBlocking);
        cudaStreamCreateWithFlags(&s3, cudaStreamNonBlocking);
        cudaEventCreateWithFlags(&evRoot, cudaEventDisableTiming);
        cudaEventCreateWithFlags(&evX,    cudaEventDisableTiming);
        cudaEventCreateWithFlags(&evW,    cudaEventDisableTiming);
        cudaEventCreateWithFlags(&evHalf, cudaEventDisableTiming);
    }

    __half *xh, *h1h, *h2h, *h3h, *Bh, *winh, *wI, *wshh, *whh, *w2h;
    float *Ac, *Bc, *Gb;
    cudaGetSymbolAddress((void**)&xh,  g_xh);
    cudaGetSymbolAddress((void**)&h1h, g_h1h);
    cudaGetSymbolAddress((void**)&h2h, g_h2h);
    cudaGetSymbolAddress((void**)&h3h, g_h3h);
    cudaGetSymbolAddress((void**)&Bh,  g_Bh);
    cudaGetSymbolAddress((void**)&winh, g_winh);
    cudaGetSymbolAddress((void**)&wI,   g_wI);
    cudaGetSymbolAddress((void**)&wshh, g_wshh);
    cudaGetSymbolAddress((void**)&whh,  g_whh);
    cudaGetSymbolAddress((void**)&w2h,  g_w2h);
    cudaGetSymbolAddress((void**)&Ac, g_Ac);
    cudaGetSymbolAddress((void**)&Bc, g_Bc);
    cudaGetSymbolAddress((void**)&Gb, g_Gb);

    const dim3 gHypH (HYP / BN,   HSEQ / BM);   //  8 x 32
    const dim3 gPairH(2*HYP / BN, HSEQ / BM);   // 16 x 32
    const dim3 gHidH (HIDN / BN,  HSEQ / BM);   // 32 x 32

    // ---- fork ----
    cudaEventRecord(evRoot, 0);
    cudaStreamWaitEvent(s2, evRoot, 0);
    cudaStreamWaitEvent(s3, evRoot, 0);

    cvtA<<<(A1/4 + 255)/256, 256>>>(x, w_in, xh, winh);
    cudaEventRecord(evX, 0);
    cvtB<<<(B3/4 + 255)/256, 256, 0, s3>>>(wg0, wg0g, wg_sh, w_h, w2,
                                           wI, wshh, whh, w2h);
    cudaEventRecord(evW, s3);

    const size_t oX  = (size_t)HSEQ * INP;
    const size_t oHy = (size_t)HSEQ * HYP;
    const size_t oHd = (size_t)HSEQ * HIDN;

    // ---- chain A (stream 0, rows 0..4095) ----
    gemm_f16<<<gHypH, NTHREADS, SMEM_DYN>>>(xh, winh, b_in, nullptr, nullptr,
                                            HYP, INP, HYP, M_PLAIN, h1h);
    cudaStreamWaitEvent(0, evW, 0);
    gemm_f16<<<gPairH, NTHREADS, SMEM_DYN>>>(h1h, wI, bg0, bg0g, nullptr,
                                             2*HYP, HYP, HYP, M_PAIR, h2h);
    gemm_f16<<<gHypH, NTHREADS, SMEM_DYN>>>(h2h, wshh, bg_sh, nullptr, nullptr,
                                            HYP, HYP, HYP, M_SILU, h3h);
    gemm_fused_gb<<<gHidH, NTHREADS, SMEM_DYN>>>(xh, w2h, h3h, whh, b2, b_h, Bh);
    scan_pass1<<<(NCHUNK/2)*HIDN/256, 256>>>(Bh, Ac, Bc, 0);

    // ---- chain B (stream s2, rows 4096..8191) ----
    cudaStreamWaitEvent(s2, evX, 0);
    gemm_f16<<<gHypH, NTHREADS, SMEM_DYN, s2>>>(xh + oX, winh, b_in, nullptr, nullptr,
                                                HYP, INP, HYP, M_PLAIN, h1h + oHy);
    cudaStreamWaitEvent(s2, evW, 0);
    gemm_f16<<<gPairH, NTHREADS, SMEM_DYN, s2>>>(h1h + oHy, wI, bg0, bg0g, nullptr,
                                                 2*HYP, HYP, HYP, M_PAIR, h2h + oHy);
    gemm_f16<<<gHypH, NTHREADS, SMEM_DYN, s2>>>(h2h + oHy, wshh, bg_sh, nullptr, nullptr,
                                                HYP, HYP, HYP, M_SILU, h3h + oHy);
    gemm_fused_gb<<<gHidH, NTHREADS, SMEM_DYN, s2>>>(xh + oX, w2h, h3h + oHy, whh,
                                                     b2, b_h, Bh + oHd);
    scan_pass1<<<(NCHUNK/2)*HIDN/256, 256, 0, s2>>>(Bh, Ac, Bc, NCHUNK/2);
    cudaEventRecord(evHalf, s2);

    // ---- join: combine + pass2 on stream 0 ----
    cudaStreamWaitEvent(0, evHalf, 0);
    scan_combine<<<HIDN/256, 256>>>(hidden, Ac, Bc, Gb);
    scan_pass2<<<NCHUNK*HIDN/256, 256>>>(Bh, Gb, out, hlast, write_h);
}